// round 8
// baseline (speedup 1.0000x reference)
#include <cuda_runtime.h>
#include <cuda_fp16.h>
#include <stdint.h>
#include <math.h>

#define NN   20000
#define EE   100000
#define DH   512
#define DOUT 256
#define HEADS 8
#define HID  64

// ---------------- scratch (device globals; no allocations allowed) ----------
__device__ float g_h   [NN * DH];
__device__ float g_h2  [NN * DH];
__device__ float g_acc3[3 * NN * DH];          // per-relation aggregation (fp32)
__device__ float g_zsum[3 * NN * HEADS];       // per-relation exp-sums

__device__ __half g_xcat16[NN * 3072];         // batched GEMM output, fp16
__device__ __half g_a16 [NN * DH];             // fp16 activation (GEMM A)
__device__ __half g_x16 [NN * DH];
__device__ __half g_w16_proj [DH * DH];
__device__ __half g_wcat01 [2 * DH * 3072];    // [li][k][ll0|ll1|ll2|lr0|lr1|lr2]
__device__ __half g_wcat2  [DH * 1536];        // [k][ll0|ll1|ll2|lr0|lr1|lr2]
__device__ float  g_bcat01 [2 * 3072];
__device__ float  g_bcat2  [1536];

// ---------------- converters / packers --------------------------------------
__global__ __launch_bounds__(256)
void f32_to_f16(const float* __restrict__ in, __half* __restrict__ out, int n4)
{
    int i = blockIdx.x * 256 + threadIdx.x;
    if (i >= n4) return;
    float4 v = ((const float4*)in)[i];
    union { __half2 h[2]; uint2 u; } p;
    p.h[0] = __floats2half2_rn(v.x, v.y);
    p.h[1] = __floats2half2_rn(v.z, v.w);
    ((uint2*)out)[i] = p.u;
}

__device__ __forceinline__ uint2 cvt4(float4 v) {
    union { __half2 h[2]; uint2 u; } p;
    p.h[0] = __floats2half2_rn(v.x, v.y);
    p.h[1] = __floats2half2_rn(v.z, v.w);
    return p.u;
}

// pack l01 weights: src [li][et][k][n] -> dst [li][k][et*512+n | 1536+et*512+n]
__global__ __launch_bounds__(256)
void pack_w01(const float* __restrict__ ll, const float* __restrict__ lr,
              __half* __restrict__ out)
{
    int i = blockIdx.x * 256 + threadIdx.x;     // float4 index
    const int TOT = 2 * 3 * DH * DH / 4;        // 393216
    if (i >= TOT) return;
    int n4 = i & 127;
    int k  = (i >> 7) & 511;
    int le = i >> 16;                            // li*3+et
    int et = le % 3, li = le / 3;
    long base = ((long)li * DH + k) * 768;       // 3072/4
    ((uint2*)out)[base + et * 128 + n4]       = cvt4(((const float4*)ll)[i]);
    ((uint2*)out)[base + 384 + et * 128 + n4] = cvt4(((const float4*)lr)[i]);
}

// pack l2 weights: src [et][k][n] -> dst [k][et*256+n | 768+et*256+n]
__global__ __launch_bounds__(256)
void pack_w2(const float* __restrict__ ll, const float* __restrict__ lr,
             __half* __restrict__ out)
{
    int i = blockIdx.x * 256 + threadIdx.x;
    const int TOT = 3 * DH * DOUT / 4;           // 98304
    if (i >= TOT) return;
    int n4 = i & 63;
    int k  = (i >> 6) & 511;
    int et = i >> 15;
    long base = (long)k * 384;                   // 1536/4
    ((uint2*)out)[base + et * 64 + n4]       = cvt4(((const float4*)ll)[i]);
    ((uint2*)out)[base + 192 + et * 64 + n4] = cvt4(((const float4*)lr)[i]);
}

__global__ __launch_bounds__(256)
void pack_b01(const float* __restrict__ ll, const float* __restrict__ lr,
              float* __restrict__ out)
{
    int i = blockIdx.x * 256 + threadIdx.x;      // 2*3*512 = 3072
    if (i >= 2 * 3 * DH) return;
    int n = i & 511;
    int le = i >> 9;
    int et = le % 3, li = le / 3;
    out[li * 3072 + et * 512 + n]        = ll[i];
    out[li * 3072 + 1536 + et * 512 + n] = lr[i];
}

__global__ __launch_bounds__(256)
void pack_b2(const float* __restrict__ ll, const float* __restrict__ lr,
             float* __restrict__ out)
{
    int i = blockIdx.x * 256 + threadIdx.x;      // 3*256 = 768
    if (i >= 3 * DOUT) return;
    int n = i & 255;
    int et = i >> 8;
    out[et * 256 + n]       = ll[i];
    out[768 + et * 256 + n] = lr[i];
}

// ---------------- fp16 HMMA GEMM, single-sync pipelined ---------------------
#define GBM 128
#define GBN 128
#define GBK 64
#define KFIX 512
#define KITERS (KFIX / GBK)        // 8
#define A_ROWB 144                 // (64+8) halves
#define B_ROWB 272                 // (128+8) halves
#define A_STAGE (GBM * A_ROWB)     // 18432 B
#define B_STAGE (GBK * B_ROWB)     // 17408 B
#define GEMM_SMEM (2 * (A_STAGE + B_STAGE))   // 71680 B

__device__ __forceinline__ uint32_t sptr(const void* p) {
    return (uint32_t)__cvta_generic_to_shared(p);
}
__device__ __forceinline__ void cp_async16(uint32_t dst, const void* src) {
    asm volatile("cp.async.cg.shared.global [%0], [%1], 16;" :: "r"(dst), "l"(src));
}
__device__ __forceinline__ void cp_commit() { asm volatile("cp.async.commit_group;"); }
template <int N> __device__ __forceinline__ void cp_wait() {
    asm volatile("cp.async.wait_group %0;" :: "n"(N));
}

__global__ __launch_bounds__(256, 2)
void hgemm_bias_act(const __half* __restrict__ A, const __half* __restrict__ B,
                    const float* __restrict__ bias, float* __restrict__ C,
                    __half* __restrict__ C16, int M, int N, int act)
{
    extern __shared__ char dsm[];
    uint32_t sA = sptr(dsm);
    uint32_t sB = sA + 2 * A_STAGE;

    int tid  = threadIdx.x;
    int lane = tid & 31;
    int wid  = tid >> 5;
    int m0 = (wid >> 2) * 64;
    int n0 = (wid & 3) * 32;
    int bx = blockIdx.x, by = blockIdx.y;

    int arow[4], aofs[4], gr[4], brow[4], bofs[4];
    #pragma unroll
    for (int i = 0; i < 4; i++) {
        int ch = tid + i * 256;
        arow[i] = ch >> 3;
        aofs[i] = (ch & 7) * 8;
        int r = by * GBM + arow[i];
        gr[i] = r < M ? r : M - 1;
        brow[i] = ch >> 4;
        bofs[i] = (ch & 15) * 8;
    }

    float acc[4][4][4];
    #pragma unroll
    for (int mi = 0; mi < 4; mi++)
        #pragma unroll
        for (int ni = 0; ni < 4; ni++)
            #pragma unroll
            for (int r = 0; r < 4; r++) acc[mi][ni][r] = 0.f;

    uint32_t a_base[4];
    #pragma unroll
    for (int mi = 0; mi < 4; mi++)
        a_base[mi] = sA + (m0 + mi * 16 + (lane & 15)) * A_ROWB + (lane >> 4) * 16;
    uint32_t b_base[4];
    #pragma unroll
    for (int ni = 0; ni < 4; ni++)
        b_base[ni] = sB + (lane & 15) * B_ROWB + (n0 + ni * 8) * 2;

    #pragma unroll
    for (int i = 0; i < 4; i++) {
        cp_async16(sA + arow[i] * A_ROWB + aofs[i] * 2,
                   A + (long)gr[i] * KFIX + aofs[i]);
        cp_async16(sB + brow[i] * B_ROWB + bofs[i] * 2,
                   B + (long)brow[i] * N + bx * GBN + bofs[i]);
    }
    cp_commit();

    for (int it = 0; it < KITERS; it++) {
        cp_wait<0>();
        __syncthreads();
        if (it + 1 < KITERS) {
            int k0 = (it + 1) * GBK;
            int st = (it + 1) & 1;
            uint32_t dA = sA + st * A_STAGE;
            uint32_t dB = sB + st * B_STAGE;
            #pragma unroll
            for (int i = 0; i < 4; i++) {
                cp_async16(dA + arow[i] * A_ROWB + aofs[i] * 2,
                           A + (long)gr[i] * KFIX + k0 + aofs[i]);
                cp_async16(dB + brow[i] * B_ROWB + bofs[i] * 2,
                           B + (long)(k0 + brow[i]) * N + bx * GBN + bofs[i]);
            }
            cp_commit();
        }

        int st = it & 1;
        uint32_t aofs_st = st * A_STAGE;
        uint32_t bofs_st = st * B_STAGE;
        #pragma unroll
        for (int ks = 0; ks < GBK; ks += 16) {
            uint32_t af[4][4], bf[4][2];
            #pragma unroll
            for (int mi = 0; mi < 4; mi++) {
                asm volatile("ldmatrix.sync.aligned.m8n8.x4.shared.b16 {%0,%1,%2,%3}, [%4];"
                             : "=r"(af[mi][0]), "=r"(af[mi][1]), "=r"(af[mi][2]), "=r"(af[mi][3])
                             : "r"(a_base[mi] + aofs_st + ks * 2));
            }
            #pragma unroll
            for (int ni = 0; ni < 4; ni++) {
                asm volatile("ldmatrix.sync.aligned.m8n8.x2.trans.shared.b16 {%0,%1}, [%2];"
                             : "=r"(bf[ni][0]), "=r"(bf[ni][1])
                             : "r"(b_base[ni] + bofs_st + ks * B_ROWB));
            }
            #pragma unroll
            for (int mi = 0; mi < 4; mi++)
                #pragma unroll
                for (int ni = 0; ni < 4; ni++) {
                    asm volatile(
                        "mma.sync.aligned.m16n8k16.row.col.f32.f16.f16.f32 "
                        "{%0,%1,%2,%3},{%4,%5,%6,%7},{%8,%9},{%0,%1,%2,%3};"
                        : "+f"(acc[mi][ni][0]), "+f"(acc[mi][ni][1]),
                          "+f"(acc[mi][ni][2]), "+f"(acc[mi][ni][3])
                        : "r"(af[mi][0]), "r"(af[mi][1]), "r"(af[mi][2]), "r"(af[mi][3]),
                          "r"(bf[ni][0]), "r"(bf[ni][1]));
                }
        }
    }

    // epilogue: bias (+ELU); optional fp32 and fp16 outputs
    #pragma unroll
    for (int mi = 0; mi < 4; mi++) {
        int r0 = by * GBM + m0 + mi * 16 + (lane >> 2);
        #pragma unroll
        for (int ni = 0; ni < 4; ni++) {
            int c = bx * GBN + n0 + ni * 8 + (lane & 3) * 2;
            float bx0 = bias[c], bx1 = bias[c + 1];
            #pragma unroll
            for (int half_ = 0; half_ < 2; half_++) {
                int r = r0 + half_ * 8;
                if (r >= M) continue;
                float v0 = acc[mi][ni][half_ * 2 + 0] + bx0;
                float v1 = acc[mi][ni][half_ * 2 + 1] + bx1;
                if (act) {
                    v0 = v0 > 0.f ? v0 : expm1f(v0);
                    v1 = v1 > 0.f ? v1 : expm1f(v1);
                }
                if (C)
                    *(float2*)(C + (long)r * N + c) = make_float2(v0, v1);
                if (C16)
                    *(__half2*)(C16 + (long)r * N + c) = __floats2half2_rn(v0, v1);
            }
        }
    }
}

// ---------------- helpers ---------------------------------------------------
__device__ __forceinline__ float warp_sum(float v) {
    #pragma unroll
    for (int o = 16; o; o >>= 1) v += __shfl_xor_sync(0xffffffffu, v, o);
    return v;
}
__device__ __forceinline__ void red_add_v4(float* p, float4 v) {
    asm volatile("red.global.add.v4.f32 [%0], {%1,%2,%3,%4};"
                 :: "l"(p), "f"(v.x), "f"(v.y), "f"(v.z), "f"(v.w) : "memory");
}
// unpack 8 halves (uint4) to 8 floats
__device__ __forceinline__ void h8_to_f8(uint4 u, float* f) {
    __half2* h = (__half2*)&u;
    float2 p0 = __half22float2(h[0]);
    float2 p1 = __half22float2(h[1]);
    float2 p2 = __half22float2(h[2]);
    float2 p3 = __half22float2(h[3]);
    f[0] = p0.x; f[1] = p0.y; f[2] = p1.x; f[3] = p1.y;
    f[4] = p2.x; f[5] = p2.y; f[6] = p3.x; f[7] = p3.y;
}

// ---------------- fused edge pass, layers 0/1 (fp16 gathers) ----------------
// warp per edge; idx=j*32+lane covers halves [8idx,8idx+8); head = idx>>3;
// 8-lane segmented reduce; fp32 red.add aggregation (deferred normalization).
__global__ __launch_bounds__(256)
void edge_fused_h8(const __half* __restrict__ xl, const __half* __restrict__ xr,
                   const int* __restrict__ src, const int* __restrict__ dst,
                   const float* __restrict__ att,   // [8][64] = 512 floats
                   float* __restrict__ acc, float* __restrict__ zsum)
{
    int e = blockIdx.x * 8 + (threadIdx.x >> 5);
    int lane = threadIdx.x & 31;
    int s = src[e], d = dst[e];
    const uint4* pl = (const uint4*)(xl + (long)s * 3072);
    const uint4* pr = (const uint4*)(xr + (long)d * 3072);
    float* accd = acc + (long)d * DH;
    #pragma unroll
    for (int j = 0; j < 2; j++) {
        int idx = j * 32 + lane;
        float a[8], b[8];
        h8_to_f8(pl[idx], a);
        h8_to_f8(pr[idx], b);
        float4 t0 = __ldg((const float4*)(att + idx * 8));
        float4 t1 = __ldg((const float4*)(att + idx * 8 + 4));
        float p = 0.f;
        const float* tt = &t0.x;
        #pragma unroll
        for (int q = 0; q < 8; q++) {
            float v = a[q] + b[q];
            v = v > 0.f ? v : 0.2f * v;
            p += v * ((q < 4) ? (&t0.x)[q] : (&t1.x)[q - 4]);
        }
        (void)tt;
        // segmented reduce over 8 lanes (one head)
        p += __shfl_xor_sync(0xffffffffu, p, 1);
        p += __shfl_xor_sync(0xffffffffu, p, 2);
        p += __shfl_xor_sync(0xffffffffu, p, 4);
        float w = expf(p);
        if ((lane & 7) == 0)
            atomicAdd(&zsum[(long)d * HEADS + (idx >> 3)], w);
        float4 v0 = make_float4(a[0] * w, a[1] * w, a[2] * w, a[3] * w);
        float4 v1 = make_float4(a[4] * w, a[5] * w, a[6] * w, a[7] * w);
        red_add_v4(accd + idx * 8, v0);
        red_add_v4(accd + idx * 8 + 4, v1);
    }
}

// ---------------- fused edge pass, layer 2 (heads=1, ch=256, fp16) ----------
__global__ __launch_bounds__(256)
void edge_fused_c256(const __half* __restrict__ xl, const __half* __restrict__ xr,
                     const int* __restrict__ src, const int* __restrict__ dst,
                     const float* __restrict__ att,   // [256]
                     float* __restrict__ acc, float* __restrict__ zsum)
{
    int e = blockIdx.x * 8 + (threadIdx.x >> 5);
    int lane = threadIdx.x & 31;
    int s = src[e], d = dst[e];
    const uint4* pl = (const uint4*)(xl + (long)s * 1536);
    const uint4* pr = (const uint4*)(xr + (long)d * 1536);
    float a[8], b[8];
    h8_to_f8(pl[lane], a);
    h8_to_f8(pr[lane], b);
    float4 t0 = __ldg((const float4*)(att + lane * 8));
    float4 t1 = __ldg((const float4*)(att + lane * 8 + 4));
    float p = 0.f;
    #pragma unroll
    for (int q = 0; q < 8; q++) {
        float v = a[q] + b[q];
        v = v > 0.f ? v : 0.2f * v;
        p += v * ((q < 4) ? (&t0.x)[q] : (&t1.x)[q - 4]);
    }
    p = warp_sum(p);
    float w = expf(p);
    if (lane == 0) atomicAdd(&zsum[d], w);
    float* accd = acc + (long)d * DOUT;
    float4 v0 = make_float4(a[0] * w, a[1] * w, a[2] * w, a[3] * w);
    float4 v1 = make_float4(a[4] * w, a[5] * w, a[6] * w, a[7] * w);
    red_add_v4(accd + lane * 8, v0);
    red_add_v4(accd + lane * 8 + 4, v1);
}

// ---------------- fused: normalize + bias + elu + residual + layernorm ------
__global__ __launch_bounds__(128)
void fuse_l01(const float* __restrict__ acc3, const float* __restrict__ z3,
              const float* __restrict__ b0, const float* __restrict__ b1,
              const float* __restrict__ b2,
              const float* __restrict__ res,
              const float* __restrict__ gamma, const float* __restrict__ beta,
              float* __restrict__ out, __half* __restrict__ out16)
{
    int i = blockIdx.x;
    int t = threadIdx.x;
    float v[4];
    float s = 0.f, s2 = 0.f;
    #pragma unroll
    for (int j = 0; j < 4; j++) {
        int c = j * 128 + t;
        int head = c >> 6;
        float x = b0[c] + b1[c] + b2[c];
        #pragma unroll
        for (int et = 0; et < 3; et++) {
            float z = z3[(long)et * NN * HEADS + (long)i * HEADS + head];
            float rz = z != 0.f ? 1.f / z : 0.f;
            x += acc3[(long)et * NN * DH + (long)i * DH + c] * rz;
        }
        x = x > 0.f ? x : expm1f(x);
        x += res[(long)i * DH + c];
        v[j] = x; s += x; s2 += x * x;
    }
    s = warp_sum(s); s2 = warp_sum(s2);
    __shared__ float sh1[4], sh2[4];
    int w = t >> 5, l = t & 31;
    if (l == 0) { sh1[w] = s; sh2[w] = s2; }
    __syncthreads();
    s = sh1[0] + sh1[1] + sh1[2] + sh1[3];
    s2 = sh2[0] + sh2[1] + sh2[2] + sh2[3];
    float mu = s * (1.f / DH);
    float var = s2 * (1.f / DH) - mu * mu;
    float inv = rsqrtf(var + 1e-5f);
    #pragma unroll
    for (int j = 0; j < 4; j++) {
        int c = j * 128 + t;
        float o = (v[j] - mu) * inv * gamma[c] + beta[c];
        out[(long)i * DH + c] = o;
        out16[(long)i * DH + c] = __float2half_rn(o);
    }
}

__global__ __launch_bounds__(128)
void fuse_l2(const float* __restrict__ acc3, const float* __restrict__ z3,
             const float* __restrict__ b0, const float* __restrict__ b1,
             const float* __restrict__ b2,
             const float* __restrict__ gamma, const float* __restrict__ beta,
             float* __restrict__ out)
{
    int i = blockIdx.x;
    int t = threadIdx.x;
    float rz[3];
    #pragma unroll
    for (int et = 0; et < 3; et++) {
        float z = z3[(long)et * NN + i];
        rz[et] = z != 0.f ? 1.f / z : 0.f;
    }
    float v[2];
    float s = 0.f, s2 = 0.f;
    #pragma unroll
    for (int j = 0; j < 2; j++) {
        int c = j * 128 + t;
        float x = b0[c] + b1[c] + b2[c];
        #pragma unroll
        for (int et = 0; et < 3; et++)
            x += acc3[(long)et * NN * DOUT + (long)i * DOUT + c] * rz[et];
        x = x > 0.f ? x : expm1f(x);
        v[j] = x; s += x; s2 += x * x;
    }
    s = warp_sum(s); s2 = warp_sum(s2);
    __shared__ float sh1[4], sh2[4];
    int w = t >> 5, l = t & 31;
    if (l == 0) { sh1[w] = s; sh2[w] = s2; }
    __syncthreads();
    s = sh1[0] + sh1[1] + sh1[2] + sh1[3];
    s2 = sh2[0] + sh2[1] + sh2[2] + sh2[3];
    float mu = s * (1.f / DOUT);
    float var = s2 * (1.f / DOUT) - mu * mu;
    float inv = rsqrtf(var + 1e-5f);
    #pragma unroll
    for (int j = 0; j < 2; j++) {
        int c = j * 128 + t;
        out[(long)i * DOUT + c] = (v[j] - mu) * inv * gamma[c] + beta[c];
    }
}

// ---------------- host ------------------------------------------------------
static inline void run_gemm(const __half* A, const __half* B, const float* bias,
                            float* C, __half* C16, int M, int N, int act)
{
    dim3 grid(N / GBN, (M + GBM - 1) / GBM);
    hgemm_bias_act<<<grid, 256, GEMM_SMEM>>>(A, B, bias, C, C16, M, N, act);
}

static inline void convert(const float* in, __half* out, long n)
{
    long n4 = n / 4;
    f32_to_f16<<<(unsigned)((n4 + 255) / 256), 256>>>(in, out, (int)n4);
}

extern "C" void kernel_launch(void* const* d_in, const int* in_sizes, int n_in,
                              void* d_out, int out_size)
{
    const float* x          = (const float*)d_in[0];
    const int*   edge_index = (const int*)  d_in[1];
    const float* proj_w     = (const float*)d_in[2];
    const float* proj_b     = (const float*)d_in[3];
    const float* l01_ll_w   = (const float*)d_in[4];
    const float* l01_ll_b   = (const float*)d_in[5];
    const float* l01_lr_w   = (const float*)d_in[6];
    const float* l01_lr_b   = (const float*)d_in[7];
    const float* l01_att    = (const float*)d_in[8];
    const float* l01_bias   = (const float*)d_in[9];
    const float* l2_ll_w    = (const float*)d_in[10];
    const float* l2_ll_b    = (const float*)d_in[11];
    const float* l2_lr_w    = (const float*)d_in[12];
    const float* l2_lr_b    = (const float*)d_in[13];
    const float* l2_att     = (const float*)d_in[14];
    const float* l2_bias    = (const float*)d_in[15];
    const float* ln01_gamma = (const float*)d_in[16];
    const float* ln01_beta  = (const float*)d_in[17];
    const float* ln2_gamma  = (const float*)d_in[18];
    const float* ln2_beta   = (const float*)d_in[19];

    float *h, *h2, *acc3, *zsum, *bcat01, *bcat2;
    __half *xcat16, *a16, *x16, *w_proj, *wcat01, *wcat2;
    cudaGetSymbolAddress((void**)&h,      g_h);
    cudaGetSymbolAddress((void**)&h2,     g_h2);
    cudaGetSymbolAddress((void**)&acc3,   g_acc3);
    cudaGetSymbolAddress((void**)&zsum,   g_zsum);
    cudaGetSymbolAddress((void**)&xcat16, g_xcat16);
    cudaGetSymbolAddress((void**)&a16,    g_a16);
    cudaGetSymbolAddress((void**)&x16,    g_x16);
    cudaGetSymbolAddress((void**)&w_proj, g_w16_proj);
    cudaGetSymbolAddress((void**)&wcat01, g_wcat01);
    cudaGetSymbolAddress((void**)&wcat2,  g_wcat2);
    cudaGetSymbolAddress((void**)&bcat01, g_bcat01);
    cudaGetSymbolAddress((void**)&bcat2,  g_bcat2);

    cudaFuncSetAttribute(hgemm_bias_act,
                         cudaFuncAttributeMaxDynamicSharedMemorySize, GEMM_SMEM);

    // one-time conversions / packs
    convert(x, x16, (long)NN * DH);
    convert(proj_w, w_proj, (long)DH * DH);
    pack_w01<<<(2 * 3 * DH * DH / 4 + 255) / 256, 256>>>(l01_ll_w, l01_lr_w, wcat01);
    pack_w2 <<<(3 * DH * DOUT / 4 + 255) / 256, 256>>>(l2_ll_w, l2_lr_w, wcat2);
    pack_b01<<<(2 * 3 * DH + 255) / 256, 256>>>(l01_ll_b, l01_lr_b, bcat01);
    pack_b2 <<<(3 * DOUT + 255) / 256, 256>>>(l2_ll_b, l2_lr_b, bcat2);

    // input projection + ELU (fp32 out h, fp16 out a16)
    run_gemm(x16, w_proj, proj_b, h, a16, NN, 512, 1);

    float* cur = h;
    float* nxt = h2;

    for (int li = 0; li < 2; li++) {
        cudaMemsetAsync(acc3, 0, (size_t)3 * NN * DH * sizeof(float));
        cudaMemsetAsync(zsum, 0, (size_t)3 * NN * HEADS * sizeof(float));
        // batched GEMM -> fp16 xcat only
        run_gemm(a16, wcat01 + (size_t)li * DH * 3072, bcat01 + (size_t)li * 3072,
                 nullptr, xcat16, NN, 3072, 0);
        for (int et = 0; et < 3; et++) {
            const int* src = edge_index + (size_t)et * 2 * EE;
            const int* dst = src + EE;
            edge_fused_h8<<<EE / 8, 256>>>(
                xcat16 + (size_t)et * 512, xcat16 + 1536 + (size_t)et * 512,
                src, dst,
                l01_att + (size_t)(li * 3 + et) * HEADS * HID,
                acc3 + (size_t)et * NN * DH,
                zsum + (size_t)et * NN * HEADS);
        }
        fuse_l01<<<NN, 128>>>(acc3, zsum,
                              l01_bias + (size_t)(li * 3 + 0) * DH,
                              l01_bias + (size_t)(li * 3 + 1) * DH,
                              l01_bias + (size_t)(li * 3 + 2) * DH,
                              cur,
                              ln01_gamma + (size_t)li * DH,
                              ln01_beta  + (size_t)li * DH,
                              nxt, a16);
        float* tmp = cur; cur = nxt; nxt = tmp;
    }

    // layer 2 (heads=1, out=256)
    cudaMemsetAsync(acc3, 0, (size_t)3 * NN * DOUT * sizeof(float));
    cudaMemsetAsync(zsum, 0, (size_t)3 * NN * sizeof(float));
    run_gemm(a16, wcat2, bcat2, nullptr, xcat16, NN, 1536, 0);
    for (int et = 0; et < 3; et++) {
        const int* src = edge_index + (size_t)et * 2 * EE;
        const int* dst = src + EE;
        edge_fused_c256<<<EE / 8, 256>>>(
            xcat16 + (size_t)et * 256, xcat16 + 768 + (size_t)et * 256,
            src, dst,
            l2_att + (size_t)et * DOUT,
            acc3 + (size_t)et * NN * DOUT,
            zsum + (size_t)et * NN);
    }
    fuse_l2<<<NN, 128>>>(acc3, zsum,
                         l2_bias + 0 * DOUT, l2_bias + 1 * DOUT, l2_bias + 2 * DOUT,
                         ln2_gamma, ln2_beta, (float*)d_out);
}

// round 9
// speedup vs baseline: 1.0510x; 1.0510x over previous
#include <cuda_runtime.h>
#include <cuda_fp16.h>
#include <stdint.h>
#include <math.h>

#define NN   20000
#define EE   100000
#define DH   512
#define DOUT 256
#define HEADS 8
#define HID  64

// ---------------- scratch (device globals; no allocations allowed) ----------
__device__ float g_h   [NN * DH];
__device__ float g_h2  [NN * DH];
__device__ float g_xcat[NN * 3072];            // batched GEMM output (fp32)
__device__ float g_acc3[3 * NN * DH];          // per-relation aggregation
__device__ float g_zsum[3 * NN * HEADS];       // per-relation exp-sums

__device__ __half g_a16 [NN * DH];             // fp16 activation (GEMM A)
__device__ __half g_x16 [NN * DH];
__device__ __half g_w16_proj [DH * DH];
__device__ __half g_wcat01 [2 * DH * 3072];    // [li][k][ll0|ll1|ll2|lr0|lr1|lr2]
__device__ __half g_wcat2  [DH * 1536];        // [k][ll0|ll1|ll2|lr0|lr1|lr2]
__device__ float  g_bcat01 [2 * 3072];
__device__ float  g_bcat2  [1536];

// ---------------- converters / packers --------------------------------------
__global__ __launch_bounds__(256)
void f32_to_f16(const float* __restrict__ in, __half* __restrict__ out, int n4)
{
    int i = blockIdx.x * 256 + threadIdx.x;
    if (i >= n4) return;
    float4 v = ((const float4*)in)[i];
    union { __half2 h[2]; uint2 u; } p;
    p.h[0] = __floats2half2_rn(v.x, v.y);
    p.h[1] = __floats2half2_rn(v.z, v.w);
    ((uint2*)out)[i] = p.u;
}

__device__ __forceinline__ uint2 cvt4(float4 v) {
    union { __half2 h[2]; uint2 u; } p;
    p.h[0] = __floats2half2_rn(v.x, v.y);
    p.h[1] = __floats2half2_rn(v.z, v.w);
    return p.u;
}

// pack l01 weights: src [li][et][k][n] -> dst [li][k][et*512+n | 1536+et*512+n]
__global__ __launch_bounds__(256)
void pack_w01(const float* __restrict__ ll, const float* __restrict__ lr,
              __half* __restrict__ out)
{
    int i = blockIdx.x * 256 + threadIdx.x;     // float4 index
    const int TOT = 2 * 3 * DH * DH / 4;        // 393216
    if (i >= TOT) return;
    int n4 = i & 127;
    int k  = (i >> 7) & 511;
    int le = i >> 16;                            // li*3+et
    int et = le % 3, li = le / 3;
    long base = ((long)li * DH + k) * 768;       // 3072/4
    ((uint2*)out)[base + et * 128 + n4]       = cvt4(((const float4*)ll)[i]);
    ((uint2*)out)[base + 384 + et * 128 + n4] = cvt4(((const float4*)lr)[i]);
}

// pack l2 weights: src [et][k][n] -> dst [k][et*256+n | 768+et*256+n]
__global__ __launch_bounds__(256)
void pack_w2(const float* __restrict__ ll, const float* __restrict__ lr,
             __half* __restrict__ out)
{
    int i = blockIdx.x * 256 + threadIdx.x;
    const int TOT = 3 * DH * DOUT / 4;           // 98304
    if (i >= TOT) return;
    int n4 = i & 63;
    int k  = (i >> 6) & 511;
    int et = i >> 15;
    long base = (long)k * 384;                   // 1536/4
    ((uint2*)out)[base + et * 64 + n4]       = cvt4(((const float4*)ll)[i]);
    ((uint2*)out)[base + 192 + et * 64 + n4] = cvt4(((const float4*)lr)[i]);
}

__global__ __launch_bounds__(256)
void pack_b01(const float* __restrict__ ll, const float* __restrict__ lr,
              float* __restrict__ out)
{
    int i = blockIdx.x * 256 + threadIdx.x;      // 2*3*512 = 3072
    if (i >= 2 * 3 * DH) return;
    int n = i & 511;
    int le = i >> 9;
    int et = le % 3, li = le / 3;
    out[li * 3072 + et * 512 + n]        = ll[i];
    out[li * 3072 + 1536 + et * 512 + n] = lr[i];
}

__global__ __launch_bounds__(256)
void pack_b2(const float* __restrict__ ll, const float* __restrict__ lr,
             float* __restrict__ out)
{
    int i = blockIdx.x * 256 + threadIdx.x;      // 3*256 = 768
    if (i >= 3 * DOUT) return;
    int n = i & 255;
    int et = i >> 8;
    out[et * 256 + n]       = ll[i];
    out[768 + et * 256 + n] = lr[i];
}

// ---------------- fp16 HMMA GEMM: 4 warps, 64x64 warp tiles -----------------
// C = act(A[Mx512] * B[512xN] + bias). 128x128 CTA tile, GBK=64, 2 stages,
// 1 sync per k-iter, cp.async for stage i+1 issued before stage i's MMAs.
// 64x64 warp tile: A-frag reuse 8 -> 128B smem per HMMA (was 192B).

#define GBM 128
#define GBN 128
#define GBK 64
#define KFIX 512
#define KITERS (KFIX / GBK)        // 8
#define A_ROWB 144                 // bytes: (64+8) halves
#define B_ROWB 272                 // bytes: (128+8) halves
#define A_STAGE (GBM * A_ROWB)     // 18432 B
#define B_STAGE (GBK * B_ROWB)     // 17408 B
#define GEMM_SMEM (2 * (A_STAGE + B_STAGE))   // 71680 B

__device__ __forceinline__ uint32_t sptr(const void* p) {
    return (uint32_t)__cvta_generic_to_shared(p);
}
__device__ __forceinline__ void cp_async16(uint32_t dst, const void* src) {
    asm volatile("cp.async.cg.shared.global [%0], [%1], 16;" :: "r"(dst), "l"(src));
}
__device__ __forceinline__ void cp_commit() { asm volatile("cp.async.commit_group;"); }
template <int N> __device__ __forceinline__ void cp_wait() {
    asm volatile("cp.async.wait_group %0;" :: "n"(N));
}

__global__ __launch_bounds__(128, 2)
void hgemm_bias_act(const __half* __restrict__ A, const __half* __restrict__ B,
                    const float* __restrict__ bias, float* __restrict__ C,
                    __half* __restrict__ C16, int M, int N, int act)
{
    extern __shared__ char dsm[];
    uint32_t sA = sptr(dsm);
    uint32_t sB = sA + 2 * A_STAGE;

    int tid  = threadIdx.x;
    int lane = tid & 31;
    int wid  = tid >> 5;              // 0..3
    int m0 = (wid >> 1) * 64;
    int n0 = (wid & 1) * 64;
    int bx = blockIdx.x, by = blockIdx.y;

    float acc[4][8][4];
    #pragma unroll
    for (int mi = 0; mi < 4; mi++)
        #pragma unroll
        for (int ni = 0; ni < 8; ni++)
            #pragma unroll
            for (int r = 0; r < 4; r++) acc[mi][ni][r] = 0.f;

    uint32_t a_base[4];
    #pragma unroll
    for (int mi = 0; mi < 4; mi++)
        a_base[mi] = sA + (m0 + mi * 16 + (lane & 15)) * A_ROWB + (lane >> 4) * 16;
    uint32_t b_base[8];
    #pragma unroll
    for (int ni = 0; ni < 8; ni++)
        b_base[ni] = sB + (lane & 15) * B_ROWB + (n0 + ni * 8) * 2;

    // staging: 1024 16B chunks per operand per stage; 8 per thread (128 thr)
    // prologue -> buffer 0, k-chunk 0
    #pragma unroll
    for (int i = 0; i < 8; i++) {
        int ch = tid + i * 128;
        int ar = ch >> 3, ao = (ch & 7) * 8;
        int r = by * GBM + ar; if (r >= M) r = M - 1;
        cp_async16(sA + ar * A_ROWB + ao * 2, A + (long)r * KFIX + ao);
        int br = ch >> 4, bo = (ch & 15) * 8;
        cp_async16(sB + br * B_ROWB + bo * 2, B + (long)br * N + bx * GBN + bo);
    }
    cp_commit();

    for (int it = 0; it < KITERS; it++) {
        cp_wait<0>();
        __syncthreads();
        if (it + 1 < KITERS) {
            int k0 = (it + 1) * GBK;
            int st = (it + 1) & 1;
            uint32_t dA = sA + st * A_STAGE;
            uint32_t dB = sB + st * B_STAGE;
            #pragma unroll
            for (int i = 0; i < 8; i++) {
                int ch = tid + i * 128;
                int ar = ch >> 3, ao = (ch & 7) * 8;
                int r = by * GBM + ar; if (r >= M) r = M - 1;
                cp_async16(dA + ar * A_ROWB + ao * 2, A + (long)r * KFIX + k0 + ao);
                int br = ch >> 4, bo = (ch & 15) * 8;
                cp_async16(dB + br * B_ROWB + bo * 2,
                           B + (long)(k0 + br) * N + bx * GBN + bo);
            }
            cp_commit();
        }

        int st = it & 1;
        uint32_t aofs_st = st * A_STAGE;
        uint32_t bofs_st = st * B_STAGE;
        #pragma unroll
        for (int ks = 0; ks < GBK; ks += 16) {
            uint32_t af[4][4], bf[8][2];
            #pragma unroll
            for (int mi = 0; mi < 4; mi++) {
                asm volatile("ldmatrix.sync.aligned.m8n8.x4.shared.b16 {%0,%1,%2,%3}, [%4];"
                             : "=r"(af[mi][0]), "=r"(af[mi][1]), "=r"(af[mi][2]), "=r"(af[mi][3])
                             : "r"(a_base[mi] + aofs_st + ks * 2));
            }
            #pragma unroll
            for (int ni = 0; ni < 8; ni++) {
                asm volatile("ldmatrix.sync.aligned.m8n8.x2.trans.shared.b16 {%0,%1}, [%2];"
                             : "=r"(bf[ni][0]), "=r"(bf[ni][1])
                             : "r"(b_base[ni] + bofs_st + ks * B_ROWB));
            }
            #pragma unroll
            for (int mi = 0; mi < 4; mi++)
                #pragma unroll
                for (int ni = 0; ni < 8; ni++) {
                    asm volatile(
                        "mma.sync.aligned.m16n8k16.row.col.f32.f16.f16.f32 "
                        "{%0,%1,%2,%3},{%4,%5,%6,%7},{%8,%9},{%0,%1,%2,%3};"
                        : "+f"(acc[mi][ni][0]), "+f"(acc[mi][ni][1]),
                          "+f"(acc[mi][ni][2]), "+f"(acc[mi][ni][3])
                        : "r"(af[mi][0]), "r"(af[mi][1]), "r"(af[mi][2]), "r"(af[mi][3]),
                          "r"(bf[ni][0]), "r"(bf[ni][1]));
                }
        }
    }

    // epilogue: bias (+ELU); optional fp32 and fp16 outputs
    #pragma unroll
    for (int mi = 0; mi < 4; mi++) {
        int r0 = by * GBM + m0 + mi * 16 + (lane >> 2);
        #pragma unroll
        for (int ni = 0; ni < 8; ni++) {
            int c = bx * GBN + n0 + ni * 8 + (lane & 3) * 2;
            float bx0 = bias[c], bx1 = bias[c + 1];
            #pragma unroll
            for (int half_ = 0; half_ < 2; half_++) {
                int r = r0 + half_ * 8;
                if (r >= M) continue;
                float v0 = acc[mi][ni][half_ * 2 + 0] + bx0;
                float v1 = acc[mi][ni][half_ * 2 + 1] + bx1;
                if (act) {
                    v0 = v0 > 0.f ? v0 : expm1f(v0);
                    v1 = v1 > 0.f ? v1 : expm1f(v1);
                }
                if (C)
                    *(float2*)(C + (long)r * N + c) = make_float2(v0, v1);
                if (C16)
                    *(__half2*)(C16 + (long)r * N + c) = __floats2half2_rn(v0, v1);
            }
        }
    }
}

// ---------------- helpers ---------------------------------------------------
__device__ __forceinline__ float warp_sum(float v) {
    #pragma unroll
    for (int o = 16; o; o >>= 1) v += __shfl_xor_sync(0xffffffffu, v, o);
    return v;
}
__device__ __forceinline__ void red_add_v4(float* p, float4 v) {
    asm volatile("red.global.add.v4.f32 [%0], {%1,%2,%3,%4};"
                 :: "l"(p), "f"(v.x), "f"(v.y), "f"(v.z), "f"(v.w) : "memory");
}

// ---------------- fused edge pass, layers 0/1 (all 3 relations, fp32) -------
// blockIdx.y = relation. warp per edge; deferred normalization.
__global__ __launch_bounds__(256)
void edge_fused_h8(const float* __restrict__ xcat,
                   const int* __restrict__ edge_index,
                   const float* __restrict__ att_base,   // li*3 relations x [8,64]
                   float* __restrict__ acc3, float* __restrict__ zsum3)
{
    int et = blockIdx.y;
    int e = blockIdx.x * 8 + (threadIdx.x >> 5);
    int lane = threadIdx.x & 31;
    const int* srcp = edge_index + (size_t)et * 2 * EE;
    int s = srcp[e], d = srcp[EE + e];
    const float4* pl = (const float4*)(xcat + (long)s * 3072 + et * 512);
    const float4* pr = (const float4*)(xcat + (long)d * 3072 + 1536 + et * 512);
    const float* att = att_base + et * 512;
    float* accd = acc3 + (long)et * NN * DH + (long)d * DH;
    float* zs   = zsum3 + (long)et * NN * HEADS + (long)d * HEADS;
    #pragma unroll
    for (int j = 0; j < 4; j++) {
        int idx = j * 32 + lane;
        float4 a = pl[idx];
        float4 b = pr[idx];
        int head = j * 2 + (lane >> 4);
        float4 t = __ldg((const float4*)(att + head * HID + (lane & 15) * 4));
        float vx = a.x + b.x; vx = vx > 0.f ? vx : 0.2f * vx;
        float vy = a.y + b.y; vy = vy > 0.f ? vy : 0.2f * vy;
        float vz = a.z + b.z; vz = vz > 0.f ? vz : 0.2f * vz;
        float vw = a.w + b.w; vw = vw > 0.f ? vw : 0.2f * vw;
        float p = vx * t.x + vy * t.y + vz * t.z + vw * t.w;
        p += __shfl_xor_sync(0xffffffffu, p, 1);
        p += __shfl_xor_sync(0xffffffffu, p, 2);
        p += __shfl_xor_sync(0xffffffffu, p, 4);
        p += __shfl_xor_sync(0xffffffffu, p, 8);
        float w = expf(p);
        if ((lane & 15) == 0)
            atomicAdd(zs + head, w);
        a.x *= w; a.y *= w; a.z *= w; a.w *= w;
        red_add_v4(accd + idx * 4, a);
    }
}

// ---------------- fused edge pass, layer 2 (all 3 relations) ----------------
__global__ __launch_bounds__(256)
void edge_fused_c256(const float* __restrict__ xcat,
                     const int* __restrict__ edge_index,
                     const float* __restrict__ att_base,   // 3 x [256]
                     float* __restrict__ acc3, float* __restrict__ zsum3)
{
    int et = blockIdx.y;
    int e = blockIdx.x * 8 + (threadIdx.x >> 5);
    int lane = threadIdx.x & 31;
    const int* srcp = edge_index + (size_t)et * 2 * EE;
    int s = srcp[e], d = srcp[EE + e];
    const float4* pl = (const float4*)(xcat + (long)s * 1536 + et * 256);
    const float4* pr = (const float4*)(xcat + (long)d * 1536 + 768 + et * 256);
    const float* att = att_base + et * 256;
    float4 a0 = pl[lane],     a1 = pl[32 + lane];
    float4 b0 = pr[lane],     b1 = pr[32 + lane];
    float4 t0 = __ldg((const float4*)(att + lane * 4));
    float4 t1 = __ldg((const float4*)(att + 128 + lane * 4));
    float p;
    {
        float vx = a0.x + b0.x; vx = vx > 0.f ? vx : 0.2f * vx;
        float vy = a0.y + b0.y; vy = vy > 0.f ? vy : 0.2f * vy;
        float vz = a0.z + b0.z; vz = vz > 0.f ? vz : 0.2f * vz;
        float vw = a0.w + b0.w; vw = vw > 0.f ? vw : 0.2f * vw;
        p = vx * t0.x + vy * t0.y + vz * t0.z + vw * t0.w;
        vx = a1.x + b1.x; vx = vx > 0.f ? vx : 0.2f * vx;
        vy = a1.y + b1.y; vy = vy > 0.f ? vy : 0.2f * vy;
        vz = a1.z + b1.z; vz = vz > 0.f ? vz : 0.2f * vz;
        vw = a1.w + b1.w; vw = vw > 0.f ? vw : 0.2f * vw;
        p += vx * t1.x + vy * t1.y + vz * t1.z + vw * t1.w;
    }
    p = warp_sum(p);
    float w = expf(p);
    if (lane == 0) atomicAdd(zsum3 + (long)et * NN + d, w);
    float* accd = acc3 + (long)et * NN * DOUT + (long)d * DOUT;
    a0.x *= w; a0.y *= w; a0.z *= w; a0.w *= w;
    a1.x *= w; a1.y *= w; a1.z *= w; a1.w *= w;
    red_add_v4(accd + lane * 4, a0);
    red_add_v4(accd + 128 + lane * 4, a1);
}

// ---------------- fused: normalize + bias + elu + residual + layernorm ------
__global__ __launch_bounds__(128)
void fuse_l01(const float* __restrict__ acc3, const float* __restrict__ z3,
              const float* __restrict__ b0, const float* __restrict__ b1,
              const float* __restrict__ b2,
              const float* __restrict__ res,
              const float* __restrict__ gamma, const float* __restrict__ beta,
              float* __restrict__ out, __half* __restrict__ out16)
{
    int i = blockIdx.x;
    int t = threadIdx.x;
    float v[4];
    float s = 0.f, s2 = 0.f;
    #pragma unroll
    for (int j = 0; j < 4; j++) {
        int c = j * 128 + t;
        int head = c >> 6;
        float x = b0[c] + b1[c] + b2[c];
        #pragma unroll
        for (int et = 0; et < 3; et++) {
            float z = z3[(long)et * NN * HEADS + (long)i * HEADS + head];
            float rz = z != 0.f ? 1.f / z : 0.f;
            x += acc3[(long)et * NN * DH + (long)i * DH + c] * rz;
        }
        x = x > 0.f ? x : expm1f(x);
        x += res[(long)i * DH + c];
        v[j] = x; s += x; s2 += x * x;
    }
    s = warp_sum(s); s2 = warp_sum(s2);
    __shared__ float sh1[4], sh2[4];
    int w = t >> 5, l = t & 31;
    if (l == 0) { sh1[w] = s; sh2[w] = s2; }
    __syncthreads();
    s = sh1[0] + sh1[1] + sh1[2] + sh1[3];
    s2 = sh2[0] + sh2[1] + sh2[2] + sh2[3];
    float mu = s * (1.f / DH);
    float var = s2 * (1.f / DH) - mu * mu;
    float inv = rsqrtf(var + 1e-5f);
    #pragma unroll
    for (int j = 0; j < 4; j++) {
        int c = j * 128 + t;
        float o = (v[j] - mu) * inv * gamma[c] + beta[c];
        out[(long)i * DH + c] = o;
        out16[(long)i * DH + c] = __float2half_rn(o);
    }
}

__global__ __launch_bounds__(128)
void fuse_l2(const float* __restrict__ acc3, const float* __restrict__ z3,
             const float* __restrict__ b0, const float* __restrict__ b1,
             const float* __restrict__ b2,
             const float* __restrict__ gamma, const float* __restrict__ beta,
             float* __restrict__ out)
{
    int i = blockIdx.x;
    int t = threadIdx.x;
    float rz[3];
    #pragma unroll
    for (int et = 0; et < 3; et++) {
        float z = z3[(long)et * NN + i];
        rz[et] = z != 0.f ? 1.f / z : 0.f;
    }
    float v[2];
    float s = 0.f, s2 = 0.f;
    #pragma unroll
    for (int j = 0; j < 2; j++) {
        int c = j * 128 + t;
        float x = b0[c] + b1[c] + b2[c];
        #pragma unroll
        for (int et = 0; et < 3; et++)
            x += acc3[(long)et * NN * DOUT + (long)i * DOUT + c] * rz[et];
        x = x > 0.f ? x : expm1f(x);
        v[j] = x; s += x; s2 += x * x;
    }
    s = warp_sum(s); s2 = warp_sum(s2);
    __shared__ float sh1[4], sh2[4];
    int w = t >> 5, l = t & 31;
    if (l == 0) { sh1[w] = s; sh2[w] = s2; }
    __syncthreads();
    s = sh1[0] + sh1[1] + sh1[2] + sh1[3];
    s2 = sh2[0] + sh2[1] + sh2[2] + sh2[3];
    float mu = s * (1.f / DOUT);
    float var = s2 * (1.f / DOUT) - mu * mu;
    float inv = rsqrtf(var + 1e-5f);
    #pragma unroll
    for (int j = 0; j < 2; j++) {
        int c = j * 128 + t;
        out[(long)i * DOUT + c] = (v[j] - mu) * inv * gamma[c] + beta[c];
    }
}

// ---------------- host ------------------------------------------------------
static inline void run_gemm(const __half* A, const __half* B, const float* bias,
                            float* C, __half* C16, int M, int N, int act)
{
    dim3 grid(N / GBN, (M + GBM - 1) / GBM);
    hgemm_bias_act<<<grid, 128, GEMM_SMEM>>>(A, B, bias, C, C16, M, N, act);
}

static inline void convert(const float* in, __half* out, long n)
{
    long n4 = n / 4;
    f32_to_f16<<<(unsigned)((n4 + 255) / 256), 256>>>(in, out, (int)n4);
}

extern "C" void kernel_launch(void* const* d_in, const int* in_sizes, int n_in,
                              void* d_out, int out_size)
{
    const float* x          = (const float*)d_in[0];
    const int*   edge_index = (const int*)  d_in[1];
    const float* proj_w     = (const float*)d_in[2];
    const float* proj_b     = (const float*)d_in[3];
    const float* l01_ll_w   = (const float*)d_in[4];
    const float* l01_ll_b   = (const float*)d_in[5];
    const float* l01_lr_w   = (const float*)d_in[6];
    const float* l01_lr_b   = (const float*)d_in[7];
    const float* l01_att    = (const float*)d_in[8];
    const float* l01_bias   = (const float*)d_in[9];
    const float* l2_ll_w    = (const float*)d_in[10];
    const float* l2_ll_b    = (const float*)d_in[11];
    const float* l2_lr_w    = (const float*)d_in[12];
    const float* l2_lr_b    = (const float*)d_in[13];
    const float* l2_att     = (const float*)d_in[14];
    const float* l2_bias    = (const float*)d_in[15];
    const float* ln01_gamma = (const float*)d_in[16];
    const float* ln01_beta  = (const float*)d_in[17];
    const float* ln2_gamma  = (const float*)d_in[18];
    const float* ln2_beta   = (const float*)d_in[19];

    float *h, *h2, *xcat, *acc3, *zsum, *bcat01, *bcat2;
    __half *a16, *x16, *w_proj, *wcat01, *wcat2;
    cudaGetSymbolAddress((void**)&h,      g_h);
    cudaGetSymbolAddress((void**)&h2,     g_h2);
    cudaGetSymbolAddress((void**)&xcat,   g_xcat);
    cudaGetSymbolAddress((void**)&acc3,   g_acc3);
    cudaGetSymbolAddress((void**)&zsum,   g_zsum);
    cudaGetSymbolAddress((void**)&a16,    g_a16);
    cudaGetSymbolAddress((void**)&x16,    g_x16);
    cudaGetSymbolAddress((void**)&w_proj, g_w16_proj);
    cudaGetSymbolAddress((void**)&wcat01, g_wcat01);
    cudaGetSymbolAddress((void**)&wcat2,  g_wcat2);
    cudaGetSymbolAddress((void**)&bcat01, g_bcat01);
    cudaGetSymbolAddress((void**)&bcat2,  g_bcat2);

    cudaFuncSetAttribute(hgemm_bias_act,
                         cudaFuncAttributeMaxDynamicSharedMemorySize, GEMM_SMEM);

    // one-time conversions / packs
    convert(x, x16, (long)NN * DH);
    convert(proj_w, w_proj, (long)DH * DH);
    pack_w01<<<(2 * 3 * DH * DH / 4 + 255) / 256, 256>>>(l01_ll_w, l01_lr_w, wcat01);
    pack_w2 <<<(3 * DH * DOUT / 4 + 255) / 256, 256>>>(l2_ll_w, l2_lr_w, wcat2);
    pack_b01<<<(2 * 3 * DH + 255) / 256, 256>>>(l01_ll_b, l01_lr_b, bcat01);
    pack_b2 <<<(3 * DOUT + 255) / 256, 256>>>(l2_ll_b, l2_lr_b, bcat2);

    // input projection + ELU (fp32 out h, fp16 out a16)
    run_gemm(x16, w_proj, proj_b, h, a16, NN, 512, 1);

    float* cur = h;
    float* nxt = h2;

    for (int li = 0; li < 2; li++) {
        cudaMemsetAsync(acc3, 0, (size_t)3 * NN * DH * sizeof(float));
        cudaMemsetAsync(zsum, 0, (size_t)3 * NN * HEADS * sizeof(float));
        run_gemm(a16, wcat01 + (size_t)li * DH * 3072, bcat01 + (size_t)li * 3072,
                 xcat, nullptr, NN, 3072, 0);
        {
            dim3 grid(EE / 8, 3);
            edge_fused_h8<<<grid, 256>>>(xcat, edge_index,
                                         l01_att + (size_t)li * 3 * HEADS * HID,
                                         acc3, zsum);
        }
        fuse_l01<<<NN, 128>>>(acc3, zsum,
                              l01_bias + (size_t)(li * 3 + 0) * DH,
                              l01_bias + (size_t)(li * 3 + 1) * DH,
                              l01_bias + (size_t)(li * 3 + 2) * DH,
                              cur,
                              ln01_gamma + (size_t)li * DH,
                              ln01_beta  + (size_t)li * DH,
                              nxt, a16);
        float* tmp = cur; cur = nxt; nxt = tmp;
    }

    // layer 2 (heads=1, out=256)
    cudaMemsetAsync(acc3, 0, (size_t)3 * NN * DOUT * sizeof(float));
    cudaMemsetAsync(zsum, 0, (size_t)3 * NN * sizeof(float));
    run_gemm(a16, wcat2, bcat2, xcat, nullptr, NN, 1536, 0);
    {
        dim3 grid(EE / 8, 3);
        edge_fused_c256<<<grid, 256>>>(xcat, edge_index, l2_att, acc3, zsum);
    }
    fuse_l2<<<NN, 128>>>(acc3, zsum,
                         l2_bias + 0 * DOUT, l2_bias + 1 * DOUT, l2_bias + 2 * DOUT,
                         ln2_gamma, ln2_beta, (float*)d_out);
}

// round 10
// speedup vs baseline: 1.2165x; 1.1575x over previous
#include <cuda_runtime.h>
#include <cuda_fp16.h>
#include <stdint.h>
#include <math.h>

#define NN   20000
#define EE   100000
#define DH   512
#define DOUT 256
#define HEADS 8
#define HID  64

// ---------------- scratch (device globals; no allocations allowed) ----------
__device__ float g_h   [NN * DH];
__device__ float g_h2  [NN * DH];
__device__ float g_xcat[NN * 3072];            // batched GEMM output (fp32)
__device__ float g_out3[3 * NN * DH];          // per-relation NORMALIZED aggregation

__device__ int   g_deg [3 * NN];
__device__ int   g_off [3 * NN];
__device__ int   g_cur [3 * NN];
__device__ int   g_csr [3 * EE];

__device__ __half g_a16 [NN * DH];             // fp16 activation (GEMM A)
__device__ __half g_x16 [NN * DH];
__device__ __half g_w16_proj [DH * DH];
__device__ __half g_wcat01 [2 * DH * 3072];    // [li][k][ll0|ll1|ll2|lr0|lr1|lr2]
__device__ __half g_wcat2  [DH * 1536];        // [k][ll0|ll1|ll2|lr0|lr1|lr2]
__device__ float  g_bcat01 [2 * 3072];
__device__ float  g_bcat2  [1536];

// ---------------- converters / packers --------------------------------------
__global__ __launch_bounds__(256)
void f32_to_f16(const float* __restrict__ in, __half* __restrict__ out, int n4)
{
    int i = blockIdx.x * 256 + threadIdx.x;
    if (i >= n4) return;
    float4 v = ((const float4*)in)[i];
    union { __half2 h[2]; uint2 u; } p;
    p.h[0] = __floats2half2_rn(v.x, v.y);
    p.h[1] = __floats2half2_rn(v.z, v.w);
    ((uint2*)out)[i] = p.u;
}

__device__ __forceinline__ uint2 cvt4(float4 v) {
    union { __half2 h[2]; uint2 u; } p;
    p.h[0] = __floats2half2_rn(v.x, v.y);
    p.h[1] = __floats2half2_rn(v.z, v.w);
    return p.u;
}

__global__ __launch_bounds__(256)
void pack_w01(const float* __restrict__ ll, const float* __restrict__ lr,
              __half* __restrict__ out)
{
    int i = blockIdx.x * 256 + threadIdx.x;
    const int TOT = 2 * 3 * DH * DH / 4;
    if (i >= TOT) return;
    int n4 = i & 127;
    int k  = (i >> 7) & 511;
    int le = i >> 16;
    int et = le % 3, li = le / 3;
    long base = ((long)li * DH + k) * 768;
    ((uint2*)out)[base + et * 128 + n4]       = cvt4(((const float4*)ll)[i]);
    ((uint2*)out)[base + 384 + et * 128 + n4] = cvt4(((const float4*)lr)[i]);
}

__global__ __launch_bounds__(256)
void pack_w2(const float* __restrict__ ll, const float* __restrict__ lr,
             __half* __restrict__ out)
{
    int i = blockIdx.x * 256 + threadIdx.x;
    const int TOT = 3 * DH * DOUT / 4;
    if (i >= TOT) return;
    int n4 = i & 63;
    int k  = (i >> 6) & 511;
    int et = i >> 15;
    long base = (long)k * 384;
    ((uint2*)out)[base + et * 64 + n4]       = cvt4(((const float4*)ll)[i]);
    ((uint2*)out)[base + 192 + et * 64 + n4] = cvt4(((const float4*)lr)[i]);
}

__global__ __launch_bounds__(256)
void pack_b01(const float* __restrict__ ll, const float* __restrict__ lr,
              float* __restrict__ out)
{
    int i = blockIdx.x * 256 + threadIdx.x;
    if (i >= 2 * 3 * DH) return;
    int n = i & 511;
    int le = i >> 9;
    int et = le % 3, li = le / 3;
    out[li * 3072 + et * 512 + n]        = ll[i];
    out[li * 3072 + 1536 + et * 512 + n] = lr[i];
}

__global__ __launch_bounds__(256)
void pack_b2(const float* __restrict__ ll, const float* __restrict__ lr,
             float* __restrict__ out)
{
    int i = blockIdx.x * 256 + threadIdx.x;
    if (i >= 3 * DOUT) return;
    int n = i & 255;
    int et = i >> 8;
    out[et * 256 + n]       = ll[i];
    out[768 + et * 256 + n] = lr[i];
}

// ---------------- CSR build (per call; edge_index fixed input) --------------
__global__ __launch_bounds__(256)
void deg_hist(const int* __restrict__ edge_index, int* __restrict__ deg)
{
    int et = blockIdx.y;
    int e = blockIdx.x * 256 + threadIdx.x;
    if (e >= EE) return;
    int d = edge_index[(size_t)et * 2 * EE + EE + e];
    atomicAdd(&deg[et * NN + d], 1);
}

// one block per et; exclusive scan of 20000 degrees -> off (+ cursor copy)
__global__ __launch_bounds__(512)
void excl_scan(const int* __restrict__ deg, int* __restrict__ off,
               int* __restrict__ cur)
{
    __shared__ int part[512];
    int et = blockIdx.x;
    const int* d = deg + et * NN;
    int* o = off + et * NN;
    int* c = cur + et * NN;
    int tid = threadIdx.x;
    const int CH = 40;                 // 512*40 >= 20000
    int base = tid * CH;
    int sum = 0;
    for (int i = 0; i < CH; i++) {
        int idx = base + i;
        if (idx < NN) sum += d[idx];
    }
    part[tid] = sum;
    __syncthreads();
    if (tid == 0) {
        int run = 0;
        for (int i = 0; i < 512; i++) { int t = part[i]; part[i] = run; run += t; }
    }
    __syncthreads();
    int run = part[tid];
    for (int i = 0; i < CH; i++) {
        int idx = base + i;
        if (idx < NN) { o[idx] = run; c[idx] = run; run += d[idx]; }
    }
}

__global__ __launch_bounds__(256)
void csr_fill(const int* __restrict__ edge_index, int* __restrict__ cur,
              int* __restrict__ csr)
{
    int et = blockIdx.y;
    int e = blockIdx.x * 256 + threadIdx.x;
    if (e >= EE) return;
    const int* sp = edge_index + (size_t)et * 2 * EE;
    int s = sp[e], d = sp[EE + e];
    int slot = atomicAdd(&cur[et * NN + d], 1);
    csr[(long)et * EE + slot] = s;
}

// ---------------- fp16 HMMA GEMM: 4 warps, 64x64 warp tiles -----------------
#define GBM 128
#define GBN 128
#define GBK 64
#define KFIX 512
#define KITERS (KFIX / GBK)
#define A_ROWB 144
#define B_ROWB 272
#define A_STAGE (GBM * A_ROWB)
#define B_STAGE (GBK * B_ROWB)
#define GEMM_SMEM (2 * (A_STAGE + B_STAGE))

__device__ __forceinline__ uint32_t sptr(const void* p) {
    return (uint32_t)__cvta_generic_to_shared(p);
}
__device__ __forceinline__ void cp_async16(uint32_t dst, const void* src) {
    asm volatile("cp.async.cg.shared.global [%0], [%1], 16;" :: "r"(dst), "l"(src));
}
__device__ __forceinline__ void cp_commit() { asm volatile("cp.async.commit_group;"); }
template <int N> __device__ __forceinline__ void cp_wait() {
    asm volatile("cp.async.wait_group %0;" :: "n"(N));
}

__global__ __launch_bounds__(128, 2)
void hgemm_bias_act(const __half* __restrict__ A, const __half* __restrict__ B,
                    const float* __restrict__ bias, float* __restrict__ C,
                    __half* __restrict__ C16, int M, int N, int act)
{
    extern __shared__ char dsm[];
    uint32_t sA = sptr(dsm);
    uint32_t sB = sA + 2 * A_STAGE;

    int tid  = threadIdx.x;
    int lane = tid & 31;
    int wid  = tid >> 5;
    int m0 = (wid >> 1) * 64;
    int n0 = (wid & 1) * 64;
    int bx = blockIdx.x, by = blockIdx.y;

    float acc[4][8][4];
    #pragma unroll
    for (int mi = 0; mi < 4; mi++)
        #pragma unroll
        for (int ni = 0; ni < 8; ni++)
            #pragma unroll
            for (int r = 0; r < 4; r++) acc[mi][ni][r] = 0.f;

    uint32_t a_base[4];
    #pragma unroll
    for (int mi = 0; mi < 4; mi++)
        a_base[mi] = sA + (m0 + mi * 16 + (lane & 15)) * A_ROWB + (lane >> 4) * 16;
    uint32_t b_base[8];
    #pragma unroll
    for (int ni = 0; ni < 8; ni++)
        b_base[ni] = sB + (lane & 15) * B_ROWB + (n0 + ni * 8) * 2;

    #pragma unroll
    for (int i = 0; i < 8; i++) {
        int ch = tid + i * 128;
        int ar = ch >> 3, ao = (ch & 7) * 8;
        int r = by * GBM + ar; if (r >= M) r = M - 1;
        cp_async16(sA + ar * A_ROWB + ao * 2, A + (long)r * KFIX + ao);
        int br = ch >> 4, bo = (ch & 15) * 8;
        cp_async16(sB + br * B_ROWB + bo * 2, B + (long)br * N + bx * GBN + bo);
    }
    cp_commit();

    for (int it = 0; it < KITERS; it++) {
        cp_wait<0>();
        __syncthreads();
        if (it + 1 < KITERS) {
            int k0 = (it + 1) * GBK;
            int st = (it + 1) & 1;
            uint32_t dA = sA + st * A_STAGE;
            uint32_t dB = sB + st * B_STAGE;
            #pragma unroll
            for (int i = 0; i < 8; i++) {
                int ch = tid + i * 128;
                int ar = ch >> 3, ao = (ch & 7) * 8;
                int r = by * GBM + ar; if (r >= M) r = M - 1;
                cp_async16(dA + ar * A_ROWB + ao * 2, A + (long)r * KFIX + k0 + ao);
                int br = ch >> 4, bo = (ch & 15) * 8;
                cp_async16(dB + br * B_ROWB + bo * 2,
                           B + (long)(k0 + br) * N + bx * GBN + bo);
            }
            cp_commit();
        }

        int st = it & 1;
        uint32_t aofs_st = st * A_STAGE;
        uint32_t bofs_st = st * B_STAGE;
        #pragma unroll
        for (int ks = 0; ks < GBK; ks += 16) {
            uint32_t af[4][4], bf[8][2];
            #pragma unroll
            for (int mi = 0; mi < 4; mi++) {
                asm volatile("ldmatrix.sync.aligned.m8n8.x4.shared.b16 {%0,%1,%2,%3}, [%4];"
                             : "=r"(af[mi][0]), "=r"(af[mi][1]), "=r"(af[mi][2]), "=r"(af[mi][3])
                             : "r"(a_base[mi] + aofs_st + ks * 2));
            }
            #pragma unroll
            for (int ni = 0; ni < 8; ni++) {
                asm volatile("ldmatrix.sync.aligned.m8n8.x2.trans.shared.b16 {%0,%1}, [%2];"
                             : "=r"(bf[ni][0]), "=r"(bf[ni][1])
                             : "r"(b_base[ni] + bofs_st + ks * B_ROWB));
            }
            #pragma unroll
            for (int mi = 0; mi < 4; mi++)
                #pragma unroll
                for (int ni = 0; ni < 8; ni++) {
                    asm volatile(
                        "mma.sync.aligned.m16n8k16.row.col.f32.f16.f16.f32 "
                        "{%0,%1,%2,%3},{%4,%5,%6,%7},{%8,%9},{%0,%1,%2,%3};"
                        : "+f"(acc[mi][ni][0]), "+f"(acc[mi][ni][1]),
                          "+f"(acc[mi][ni][2]), "+f"(acc[mi][ni][3])
                        : "r"(af[mi][0]), "r"(af[mi][1]), "r"(af[mi][2]), "r"(af[mi][3]),
                          "r"(bf[ni][0]), "r"(bf[ni][1]));
                }
        }
    }

    #pragma unroll
    for (int mi = 0; mi < 4; mi++) {
        int r0 = by * GBM + m0 + mi * 16 + (lane >> 2);
        #pragma unroll
        for (int ni = 0; ni < 8; ni++) {
            int c = bx * GBN + n0 + ni * 8 + (lane & 3) * 2;
            float bx0 = bias[c], bx1 = bias[c + 1];
            #pragma unroll
            for (int half_ = 0; half_ < 2; half_++) {
                int r = r0 + half_ * 8;
                if (r >= M) continue;
                float v0 = acc[mi][ni][half_ * 2 + 0] + bx0;
                float v1 = acc[mi][ni][half_ * 2 + 1] + bx1;
                if (act) {
                    v0 = v0 > 0.f ? v0 : expm1f(v0);
                    v1 = v1 > 0.f ? v1 : expm1f(v1);
                }
                if (C)
                    *(float2*)(C + (long)r * N + c) = make_float2(v0, v1);
                if (C16)
                    *(__half2*)(C16 + (long)r * N + c) = __floats2half2_rn(v0, v1);
            }
        }
    }
}

// ---------------- helpers ---------------------------------------------------
__device__ __forceinline__ float warp_sum(float v) {
    #pragma unroll
    for (int o = 16; o; o >>= 1) v += __shfl_xor_sync(0xffffffffu, v, o);
    return v;
}

// ---------------- CSR aggregation, layers 0/1 -------------------------------
// warp per (dst, et). xr resident in registers; loop incoming edges; write
// normalized result (no atomics, no memset needed).
__global__ __launch_bounds__(256)
void agg_h8(const float* __restrict__ xcat,
            const int* __restrict__ off, const int* __restrict__ deg,
            const int* __restrict__ csr,
            const float* __restrict__ att_base,
            float* __restrict__ out3)
{
    int et = blockIdx.y;
    int d = blockIdx.x * 8 + (threadIdx.x >> 5);
    int lane = threadIdx.x & 31;

    int o = off[et * NN + d];
    int n = deg[et * NN + d];
    const float* att = att_base + et * 512;
    const float4* pr = (const float4*)(xcat + (long)d * 3072 + 1536 + et * 512);

    float4 xr[4], t[4];
    #pragma unroll
    for (int j = 0; j < 4; j++) {
        int idx = j * 32 + lane;
        xr[j] = pr[idx];
        t[j] = __ldg((const float4*)(att + (j * 2 + (lane >> 4)) * HID + (lane & 15) * 4));
    }
    float accv[4][4];
    float z[4] = {0.f, 0.f, 0.f, 0.f};
    #pragma unroll
    for (int j = 0; j < 4; j++)
        #pragma unroll
        for (int q = 0; q < 4; q++) accv[j][q] = 0.f;

    const int* srcs = csr + (long)et * EE + o;
    for (int k = 0; k < n; k++) {
        int s = srcs[k];
        const float4* pl = (const float4*)(xcat + (long)s * 3072 + et * 512);
        float4 a[4];
        #pragma unroll
        for (int j = 0; j < 4; j++) a[j] = pl[j * 32 + lane];
        #pragma unroll
        for (int j = 0; j < 4; j++) {
            float vx = a[j].x + xr[j].x; vx = vx > 0.f ? vx : 0.2f * vx;
            float vy = a[j].y + xr[j].y; vy = vy > 0.f ? vy : 0.2f * vy;
            float vz = a[j].z + xr[j].z; vz = vz > 0.f ? vz : 0.2f * vz;
            float vw = a[j].w + xr[j].w; vw = vw > 0.f ? vw : 0.2f * vw;
            float p = vx * t[j].x + vy * t[j].y + vz * t[j].z + vw * t[j].w;
            p += __shfl_xor_sync(0xffffffffu, p, 1);
            p += __shfl_xor_sync(0xffffffffu, p, 2);
            p += __shfl_xor_sync(0xffffffffu, p, 4);
            p += __shfl_xor_sync(0xffffffffu, p, 8);
            float w = expf(p);
            z[j] += w;
            accv[j][0] += w * a[j].x;
            accv[j][1] += w * a[j].y;
            accv[j][2] += w * a[j].z;
            accv[j][3] += w * a[j].w;
        }
    }

    float* od = out3 + (long)et * NN * DH + (long)d * DH;
    #pragma unroll
    for (int j = 0; j < 4; j++) {
        float rz = z[j] != 0.f ? 1.f / z[j] : 0.f;
        float4 v = make_float4(accv[j][0] * rz, accv[j][1] * rz,
                               accv[j][2] * rz, accv[j][3] * rz);
        *(float4*)(od + (j * 32 + lane) * 4) = v;
    }
}

// ---------------- CSR aggregation, layer 2 (heads=1, ch=256) ----------------
__global__ __launch_bounds__(256)
void agg_c256(const float* __restrict__ xcat,
              const int* __restrict__ off, const int* __restrict__ deg,
              const int* __restrict__ csr,
              const float* __restrict__ att_base,
              float* __restrict__ out3)
{
    int et = blockIdx.y;
    int d = blockIdx.x * 8 + (threadIdx.x >> 5);
    int lane = threadIdx.x & 31;

    int o = off[et * NN + d];
    int n = deg[et * NN + d];
    const float* att = att_base + et * 256;
    const float4* pr = (const float4*)(xcat + (long)d * 1536 + 768 + et * 256);

    float4 xr0 = pr[lane], xr1 = pr[32 + lane];
    float4 t0 = __ldg((const float4*)(att + lane * 4));
    float4 t1 = __ldg((const float4*)(att + 128 + lane * 4));

    float acc0[4] = {0.f, 0.f, 0.f, 0.f};
    float acc1[4] = {0.f, 0.f, 0.f, 0.f};
    float z = 0.f;

    const int* srcs = csr + (long)et * EE + o;
    for (int k = 0; k < n; k++) {
        int s = srcs[k];
        const float4* pl = (const float4*)(xcat + (long)s * 1536 + et * 256);
        float4 a0 = pl[lane], a1 = pl[32 + lane];
        float vx = a0.x + xr0.x; vx = vx > 0.f ? vx : 0.2f * vx;
        float vy = a0.y + xr0.y; vy = vy > 0.f ? vy : 0.2f * vy;
        float vz = a0.z + xr0.z; vz = vz > 0.f ? vz : 0.2f * vz;
        float vw = a0.w + xr0.w; vw = vw > 0.f ? vw : 0.2f * vw;
        float p = vx * t0.x + vy * t0.y + vz * t0.z + vw * t0.w;
        vx = a1.x + xr1.x; vx = vx > 0.f ? vx : 0.2f * vx;
        vy = a1.y + xr1.y; vy = vy > 0.f ? vy : 0.2f * vy;
        vz = a1.z + xr1.z; vz = vz > 0.f ? vz : 0.2f * vz;
        vw = a1.w + xr1.w; vw = vw > 0.f ? vw : 0.2f * vw;
        p += vx * t1.x + vy * t1.y + vz * t1.z + vw * t1.w;
        p = warp_sum(p);
        float w = expf(p);
        z += w;
        acc0[0] += w * a0.x; acc0[1] += w * a0.y;
        acc0[2] += w * a0.z; acc0[3] += w * a0.w;
        acc1[0] += w * a1.x; acc1[1] += w * a1.y;
        acc1[2] += w * a1.z; acc1[3] += w * a1.w;
    }

    float rz = z != 0.f ? 1.f / z : 0.f;
    float* od = out3 + (long)et * NN * DOUT + (long)d * DOUT;
    *(float4*)(od + lane * 4) =
        make_float4(acc0[0] * rz, acc0[1] * rz, acc0[2] * rz, acc0[3] * rz);
    *(float4*)(od + 128 + lane * 4) =
        make_float4(acc1[0] * rz, acc1[1] * rz, acc1[2] * rz, acc1[3] * rz);
}

// ---------------- fused: sum relations + bias + elu + residual + layernorm --
__global__ __launch_bounds__(128)
void fuse_l01(const float* __restrict__ out3,
              const float* __restrict__ b0, const float* __restrict__ b1,
              const float* __restrict__ b2,
              const float* __restrict__ res,
              const float* __restrict__ gamma, const float* __restrict__ beta,
              float* __restrict__ out, __half* __restrict__ out16)
{
    int i = blockIdx.x;
    int t = threadIdx.x;
    float v[4];
    float s = 0.f, s2 = 0.f;
    #pragma unroll
    for (int j = 0; j < 4; j++) {
        int c = j * 128 + t;
        float x = b0[c] + b1[c] + b2[c];
        #pragma unroll
        for (int et = 0; et < 3; et++)
            x += out3[(long)et * NN * DH + (long)i * DH + c];
        x = x > 0.f ? x : expm1f(x);
        x += res[(long)i * DH + c];
        v[j] = x; s += x; s2 += x * x;
    }
    s = warp_sum(s); s2 = warp_sum(s2);
    __shared__ float sh1[4], sh2[4];
    int w = t >> 5, l = t & 31;
    if (l == 0) { sh1[w] = s; sh2[w] = s2; }
    __syncthreads();
    s = sh1[0] + sh1[1] + sh1[2] + sh1[3];
    s2 = sh2[0] + sh2[1] + sh2[2] + sh2[3];
    float mu = s * (1.f / DH);
    float var = s2 * (1.f / DH) - mu * mu;
    float inv = rsqrtf(var + 1e-5f);
    #pragma unroll
    for (int j = 0; j < 4; j++) {
        int c = j * 128 + t;
        float o = (v[j] - mu) * inv * gamma[c] + beta[c];
        out[(long)i * DH + c] = o;
        out16[(long)i * DH + c] = __float2half_rn(o);
    }
}

__global__ __launch_bounds__(128)
void fuse_l2(const float* __restrict__ out3,
             const float* __restrict__ b0, const float* __restrict__ b1,
             const float* __restrict__ b2,
             const float* __restrict__ gamma, const float* __restrict__ beta,
             float* __restrict__ out)
{
    int i = blockIdx.x;
    int t = threadIdx.x;
    float v[2];
    float s = 0.f, s2 = 0.f;
    #pragma unroll
    for (int j = 0; j < 2; j++) {
        int c = j * 128 + t;
        float x = b0[c] + b1[c] + b2[c];
        #pragma unroll
        for (int et = 0; et < 3; et++)
            x += out3[(long)et * NN * DOUT + (long)i * DOUT + c];
        x = x > 0.f ? x : expm1f(x);
        v[j] = x; s += x; s2 += x * x;
    }
    s = warp_sum(s); s2 = warp_sum(s2);
    __shared__ float sh1[4], sh2[4];
    int w = t >> 5, l = t & 31;
    if (l == 0) { sh1[w] = s; sh2[w] = s2; }
    __syncthreads();
    s = sh1[0] + sh1[1] + sh1[2] + sh1[3];
    s2 = sh2[0] + sh2[1] + sh2[2] + sh2[3];
    float mu = s * (1.f / DOUT);
    float var = s2 * (1.f / DOUT) - mu * mu;
    float inv = rsqrtf(var + 1e-5f);
    #pragma unroll
    for (int j = 0; j < 2; j++) {
        int c = j * 128 + t;
        out[(long)i * DOUT + c] = (v[j] - mu) * inv * gamma[c] + beta[c];
    }
}

// ---------------- host ------------------------------------------------------
static inline void run_gemm(const __half* A, const __half* B, const float* bias,
                            float* C, __half* C16, int M, int N, int act)
{
    dim3 grid(N / GBN, (M + GBM - 1) / GBM);
    hgemm_bias_act<<<grid, 128, GEMM_SMEM>>>(A, B, bias, C, C16, M, N, act);
}

static inline void convert(const float* in, __half* out, long n)
{
    long n4 = n / 4;
    f32_to_f16<<<(unsigned)((n4 + 255) / 256), 256>>>(in, out, (int)n4);
}

extern "C" void kernel_launch(void* const* d_in, const int* in_sizes, int n_in,
                              void* d_out, int out_size)
{
    const float* x          = (const float*)d_in[0];
    const int*   edge_index = (const int*)  d_in[1];
    const float* proj_w     = (const float*)d_in[2];
    const float* proj_b     = (const float*)d_in[3];
    const float* l01_ll_w   = (const float*)d_in[4];
    const float* l01_ll_b   = (const float*)d_in[5];
    const float* l01_lr_w   = (const float*)d_in[6];
    const float* l01_lr_b   = (const float*)d_in[7];
    const float* l01_att    = (const float*)d_in[8];
    const float* l01_bias   = (const float*)d_in[9];
    const float* l2_ll_w    = (const float*)d_in[10];
    const float* l2_ll_b    = (const float*)d_in[11];
    const float* l2_lr_w    = (const float*)d_in[12];
    const float* l2_lr_b    = (const float*)d_in[13];
    const float* l2_att     = (const float*)d_in[14];
    const float* l2_bias    = (const float*)d_in[15];
    const float* ln01_gamma = (const float*)d_in[16];
    const float* ln01_beta  = (const float*)d_in[17];
    const float* ln2_gamma  = (const float*)d_in[18];
    const float* ln2_beta   = (const float*)d_in[19];

    float *h, *h2, *xcat, *out3, *bcat01, *bcat2;
    int *deg, *off, *cur, *csr;
    __half *a16, *x16, *w_proj, *wcat01, *wcat2;
    cudaGetSymbolAddress((void**)&h,      g_h);
    cudaGetSymbolAddress((void**)&h2,     g_h2);
    cudaGetSymbolAddress((void**)&xcat,   g_xcat);
    cudaGetSymbolAddress((void**)&out3,   g_out3);
    cudaGetSymbolAddress((void**)&deg,    g_deg);
    cudaGetSymbolAddress((void**)&off,    g_off);
    cudaGetSymbolAddress((void**)&cur,    g_cur);
    cudaGetSymbolAddress((void**)&csr,    g_csr);
    cudaGetSymbolAddress((void**)&a16,    g_a16);
    cudaGetSymbolAddress((void**)&x16,    g_x16);
    cudaGetSymbolAddress((void**)&w_proj, g_w16_proj);
    cudaGetSymbolAddress((void**)&wcat01, g_wcat01);
    cudaGetSymbolAddress((void**)&wcat2,  g_wcat2);
    cudaGetSymbolAddress((void**)&bcat01, g_bcat01);
    cudaGetSymbolAddress((void**)&bcat2,  g_bcat2);

    cudaFuncSetAttribute(hgemm_bias_act,
                         cudaFuncAttributeMaxDynamicSharedMemorySize, GEMM_SMEM);

    // one-time conversions / packs
    convert(x, x16, (long)NN * DH);
    convert(proj_w, w_proj, (long)DH * DH);
    pack_w01<<<(2 * 3 * DH * DH / 4 + 255) / 256, 256>>>(l01_ll_w, l01_lr_w, wcat01);
    pack_w2 <<<(3 * DH * DOUT / 4 + 255) / 256, 256>>>(l2_ll_w, l2_lr_w, wcat2);
    pack_b01<<<(2 * 3 * DH + 255) / 256, 256>>>(l01_ll_b, l01_lr_b, bcat01);
    pack_b2 <<<(3 * DOUT + 255) / 256, 256>>>(l2_ll_b, l2_lr_b, bcat2);

    // CSR build (reused by all 3 layers)
    cudaMemsetAsync(deg, 0, (size_t)3 * NN * sizeof(int));
    {
        dim3 grid((EE + 255) / 256, 3);
        deg_hist<<<grid, 256>>>(edge_index, deg);
        excl_scan<<<3, 512>>>(deg, off, cur);
        csr_fill<<<grid, 256>>>(edge_index, cur, csr);
    }

    // input projection + ELU (fp32 out h, fp16 out a16)
    run_gemm(x16, w_proj, proj_b, h, a16, NN, 512, 1);

    float* curh = h;
    float* nxt = h2;

    for (int li = 0; li < 2; li++) {
        run_gemm(a16, wcat01 + (size_t)li * DH * 3072, bcat01 + (size_t)li * 3072,
                 xcat, nullptr, NN, 3072, 0);
        {
            dim3 grid(NN / 8, 3);
            agg_h8<<<grid, 256>>>(xcat, off, deg, csr,
                                  l01_att + (size_t)li * 3 * HEADS * HID, out3);
        }
        fuse_l01<<<NN, 128>>>(out3,
                              l01_bias + (size_t)(li * 3 + 0) * DH,
                              l01_bias + (size_t)(li * 3 + 1) * DH,
                              l01_bias + (size_t)(li * 3 + 2) * DH,
                              curh,
                              ln01_gamma + (size_t)li * DH,
                              ln01_beta  + (size_t)li * DH,
                              nxt, a16);
        float* tmp = curh; curh = nxt; nxt = tmp;
    }

    // layer 2 (heads=1, out=256)
    run_gemm(a16, wcat2, bcat2, xcat, nullptr, NN, 1536, 0);
    {
        dim3 grid(NN / 8, 3);
        agg_c256<<<grid, 256>>>(xcat, off, deg, csr, l2_att, out3);
    }
    fuse_l2<<<NN, 128>>>(out3,
                         l2_bias + 0 * DOUT, l2_bias + 1 * DOUT, l2_bias + 2 * DOUT,
                         ln2_gamma, ln2_beta, (float*)d_out);
}

// round 11
// speedup vs baseline: 1.2459x; 1.0242x over previous
#include <cuda_runtime.h>
#include <cuda_fp16.h>
#include <stdint.h>
#include <math.h>

#define NN   20000
#define EE   100000
#define DH   512
#define DOUT 256
#define HEADS 8
#define HID  64

// ---------------- scratch (device globals; no allocations allowed) ----------
__device__ float g_h   [NN * DH];
__device__ float g_h2  [NN * DH];
__device__ float g_xcat[NN * 3072];            // batched GEMM output (fp32)

__device__ int   g_deg [3 * NN];
__device__ int   g_off [3 * NN];
__device__ int   g_cur [3 * NN];
__device__ int   g_csr [3 * EE];

__device__ __half g_a16 [NN * DH];             // fp16 activation (GEMM A)
__device__ __half g_x16 [NN * DH];
__device__ __half g_w16_proj [DH * DH];
__device__ __half g_wcat01 [2 * DH * 3072];
__device__ __half g_wcat2  [DH * 1536];
__device__ float  g_bcat01 [2 * 3072];
__device__ float  g_bcat2  [1536];

// ---------------- converters / packers --------------------------------------
__global__ __launch_bounds__(256)
void f32_to_f16(const float* __restrict__ in, __half* __restrict__ out, int n4)
{
    int i = blockIdx.x * 256 + threadIdx.x;
    if (i >= n4) return;
    float4 v = ((const float4*)in)[i];
    union { __half2 h[2]; uint2 u; } p;
    p.h[0] = __floats2half2_rn(v.x, v.y);
    p.h[1] = __floats2half2_rn(v.z, v.w);
    ((uint2*)out)[i] = p.u;
}

__device__ __forceinline__ uint2 cvt4(float4 v) {
    union { __half2 h[2]; uint2 u; } p;
    p.h[0] = __floats2half2_rn(v.x, v.y);
    p.h[1] = __floats2half2_rn(v.z, v.w);
    return p.u;
}

__global__ __launch_bounds__(256)
void pack_w01(const float* __restrict__ ll, const float* __restrict__ lr,
              __half* __restrict__ out)
{
    int i = blockIdx.x * 256 + threadIdx.x;
    const int TOT = 2 * 3 * DH * DH / 4;
    if (i >= TOT) return;
    int n4 = i & 127;
    int k  = (i >> 7) & 511;
    int le = i >> 16;
    int et = le % 3, li = le / 3;
    long base = ((long)li * DH + k) * 768;
    ((uint2*)out)[base + et * 128 + n4]       = cvt4(((const float4*)ll)[i]);
    ((uint2*)out)[base + 384 + et * 128 + n4] = cvt4(((const float4*)lr)[i]);
}

__global__ __launch_bounds__(256)
void pack_w2(const float* __restrict__ ll, const float* __restrict__ lr,
             __half* __restrict__ out)
{
    int i = blockIdx.x * 256 + threadIdx.x;
    const int TOT = 3 * DH * DOUT / 4;
    if (i >= TOT) return;
    int n4 = i & 63;
    int k  = (i >> 6) & 511;
    int et = i >> 15;
    long base = (long)k * 384;
    ((uint2*)out)[base + et * 64 + n4]       = cvt4(((const float4*)ll)[i]);
    ((uint2*)out)[base + 192 + et * 64 + n4] = cvt4(((const float4*)lr)[i]);
}

__global__ __launch_bounds__(256)
void pack_b01(const float* __restrict__ ll, const float* __restrict__ lr,
              float* __restrict__ out)
{
    int i = blockIdx.x * 256 + threadIdx.x;
    if (i >= 2 * 3 * DH) return;
    int n = i & 511;
    int le = i >> 9;
    int et = le % 3, li = le / 3;
    out[li * 3072 + et * 512 + n]        = ll[i];
    out[li * 3072 + 1536 + et * 512 + n] = lr[i];
}

__global__ __launch_bounds__(256)
void pack_b2(const float* __restrict__ ll, const float* __restrict__ lr,
             float* __restrict__ out)
{
    int i = blockIdx.x * 256 + threadIdx.x;
    if (i >= 3 * DOUT) return;
    int n = i & 255;
    int et = i >> 8;
    out[et * 256 + n]       = ll[i];
    out[768 + et * 256 + n] = lr[i];
}

// ---------------- CSR build (per call; edge_index fixed input) --------------
__global__ __launch_bounds__(256)
void deg_hist(const int* __restrict__ edge_index, int* __restrict__ deg)
{
    int et = blockIdx.y;
    int e = blockIdx.x * 256 + threadIdx.x;
    if (e >= EE) return;
    int d = edge_index[(size_t)et * 2 * EE + EE + e];
    atomicAdd(&deg[et * NN + d], 1);
}

__global__ __launch_bounds__(512)
void excl_scan(const int* __restrict__ deg, int* __restrict__ off,
               int* __restrict__ cur)
{
    __shared__ int part[512];
    int et = blockIdx.x;
    const int* d = deg + et * NN;
    int* o = off + et * NN;
    int* c = cur + et * NN;
    int tid = threadIdx.x;
    const int CH = 40;
    int base = tid * CH;
    int sum = 0;
    for (int i = 0; i < CH; i++) {
        int idx = base + i;
        if (idx < NN) sum += d[idx];
    }
    part[tid] = sum;
    __syncthreads();
    if (tid == 0) {
        int run = 0;
        for (int i = 0; i < 512; i++) { int t = part[i]; part[i] = run; run += t; }
    }
    __syncthreads();
    int run = part[tid];
    for (int i = 0; i < CH; i++) {
        int idx = base + i;
        if (idx < NN) { o[idx] = run; c[idx] = run; run += d[idx]; }
    }
}

__global__ __launch_bounds__(256)
void csr_fill(const int* __restrict__ edge_index, int* __restrict__ cur,
              int* __restrict__ csr)
{
    int et = blockIdx.y;
    int e = blockIdx.x * 256 + threadIdx.x;
    if (e >= EE) return;
    const int* sp = edge_index + (size_t)et * 2 * EE;
    int s = sp[e], d = sp[EE + e];
    int slot = atomicAdd(&cur[et * NN + d], 1);
    csr[(long)et * EE + slot] = s;
}

// ---------------- fp16 HMMA GEMM: 4 warps, 64x64 warp tiles -----------------
#define GBM 128
#define GBN 128
#define GBK 64
#define KFIX 512
#define KITERS (KFIX / GBK)
#define A_ROWB 144
#define B_ROWB 272
#define A_STAGE (GBM * A_ROWB)
#define B_STAGE (GBK * B_ROWB)
#define GEMM_SMEM (2 * (A_STAGE + B_STAGE))

__device__ __forceinline__ uint32_t sptr(const void* p) {
    return (uint32_t)__cvta_generic_to_shared(p);
}
__device__ __forceinline__ void cp_async16(uint32_t dst, const void* src) {
    asm volatile("cp.async.cg.shared.global [%0], [%1], 16;" :: "r"(dst), "l"(src));
}
__device__ __forceinline__ void cp_commit() { asm volatile("cp.async.commit_group;"); }
template <int N> __device__ __forceinline__ void cp_wait() {
    asm volatile("cp.async.wait_group %0;" :: "n"(N));
}

__global__ __launch_bounds__(128, 2)
void hgemm_bias_act(const __half* __restrict__ A, const __half* __restrict__ B,
                    const float* __restrict__ bias, float* __restrict__ C,
                    __half* __restrict__ C16, int M, int N, int act)
{
    extern __shared__ char dsm[];
    uint32_t sA = sptr(dsm);
    uint32_t sB = sA + 2 * A_STAGE;

    int tid  = threadIdx.x;
    int lane = tid & 31;
    int wid  = tid >> 5;
    int m0 = (wid >> 1) * 64;
    int n0 = (wid & 1) * 64;
    int bx = blockIdx.x, by = blockIdx.y;

    float acc[4][8][4];
    #pragma unroll
    for (int mi = 0; mi < 4; mi++)
        #pragma unroll
        for (int ni = 0; ni < 8; ni++)
            #pragma unroll
            for (int r = 0; r < 4; r++) acc[mi][ni][r] = 0.f;

    uint32_t a_base[4];
    #pragma unroll
    for (int mi = 0; mi < 4; mi++)
        a_base[mi] = sA + (m0 + mi * 16 + (lane & 15)) * A_ROWB + (lane >> 4) * 16;
    uint32_t b_base[8];
    #pragma unroll
    for (int ni = 0; ni < 8; ni++)
        b_base[ni] = sB + (lane & 15) * B_ROWB + (n0 + ni * 8) * 2;

    #pragma unroll
    for (int i = 0; i < 8; i++) {
        int ch = tid + i * 128;
        int ar = ch >> 3, ao = (ch & 7) * 8;
        int r = by * GBM + ar; if (r >= M) r = M - 1;
        cp_async16(sA + ar * A_ROWB + ao * 2, A + (long)r * KFIX + ao);
        int br = ch >> 4, bo = (ch & 15) * 8;
        cp_async16(sB + br * B_ROWB + bo * 2, B + (long)br * N + bx * GBN + bo);
    }
    cp_commit();

    for (int it = 0; it < KITERS; it++) {
        cp_wait<0>();
        __syncthreads();
        if (it + 1 < KITERS) {
            int k0 = (it + 1) * GBK;
            int st = (it + 1) & 1;
            uint32_t dA = sA + st * A_STAGE;
            uint32_t dB = sB + st * B_STAGE;
            #pragma unroll
            for (int i = 0; i < 8; i++) {
                int ch = tid + i * 128;
                int ar = ch >> 3, ao = (ch & 7) * 8;
                int r = by * GBM + ar; if (r >= M) r = M - 1;
                cp_async16(dA + ar * A_ROWB + ao * 2, A + (long)r * KFIX + k0 + ao);
                int br = ch >> 4, bo = (ch & 15) * 8;
                cp_async16(dB + br * B_ROWB + bo * 2,
                           B + (long)(k0 + br) * N + bx * GBN + bo);
            }
            cp_commit();
        }

        int st = it & 1;
        uint32_t aofs_st = st * A_STAGE;
        uint32_t bofs_st = st * B_STAGE;
        #pragma unroll
        for (int ks = 0; ks < GBK; ks += 16) {
            uint32_t af[4][4], bf[8][2];
            #pragma unroll
            for (int mi = 0; mi < 4; mi++) {
                asm volatile("ldmatrix.sync.aligned.m8n8.x4.shared.b16 {%0,%1,%2,%3}, [%4];"
                             : "=r"(af[mi][0]), "=r"(af[mi][1]), "=r"(af[mi][2]), "=r"(af[mi][3])
                             : "r"(a_base[mi] + aofs_st + ks * 2));
            }
            #pragma unroll
            for (int ni = 0; ni < 8; ni++) {
                asm volatile("ldmatrix.sync.aligned.m8n8.x2.trans.shared.b16 {%0,%1}, [%2];"
                             : "=r"(bf[ni][0]), "=r"(bf[ni][1])
                             : "r"(b_base[ni] + bofs_st + ks * B_ROWB));
            }
            #pragma unroll
            for (int mi = 0; mi < 4; mi++)
                #pragma unroll
                for (int ni = 0; ni < 8; ni++) {
                    asm volatile(
                        "mma.sync.aligned.m16n8k16.row.col.f32.f16.f16.f32 "
                        "{%0,%1,%2,%3},{%4,%5,%6,%7},{%8,%9},{%0,%1,%2,%3};"
                        : "+f"(acc[mi][ni][0]), "+f"(acc[mi][ni][1]),
                          "+f"(acc[mi][ni][2]), "+f"(acc[mi][ni][3])
                        : "r"(af[mi][0]), "r"(af[mi][1]), "r"(af[mi][2]), "r"(af[mi][3]),
                          "r"(bf[ni][0]), "r"(bf[ni][1]));
                }
        }
    }

    #pragma unroll
    for (int mi = 0; mi < 4; mi++) {
        int r0 = by * GBM + m0 + mi * 16 + (lane >> 2);
        #pragma unroll
        for (int ni = 0; ni < 8; ni++) {
            int c = bx * GBN + n0 + ni * 8 + (lane & 3) * 2;
            float bx0 = bias[c], bx1 = bias[c + 1];
            #pragma unroll
            for (int half_ = 0; half_ < 2; half_++) {
                int r = r0 + half_ * 8;
                if (r >= M) continue;
                float v0 = acc[mi][ni][half_ * 2 + 0] + bx0;
                float v1 = acc[mi][ni][half_ * 2 + 1] + bx1;
                if (act) {
                    v0 = v0 > 0.f ? v0 : expm1f(v0);
                    v1 = v1 > 0.f ? v1 : expm1f(v1);
                }
                if (C)
                    *(float2*)(C + (long)r * N + c) = make_float2(v0, v1);
                if (C16)
                    *(__half2*)(C16 + (long)r * N + c) = __floats2half2_rn(v0, v1);
            }
        }
    }
}

// ---------------- helpers ---------------------------------------------------
__device__ __forceinline__ float warp_sum(float v) {
    #pragma unroll
    for (int o = 16; o; o >>= 1) v += __shfl_xor_sync(0xffffffffu, v, o);
    return v;
}

// ---------------- FULLY FUSED layer 0/1: agg(3 rel) + bias + ELU + res + LN -
// warp per dst node; warp holds the whole 512-ch row in registers.
__global__ __launch_bounds__(256)
void agg_fuse_l01(const float* __restrict__ xcat,
                  const int* __restrict__ off, const int* __restrict__ deg,
                  const int* __restrict__ csr,
                  const float* __restrict__ att_base,   // 3 x [8][64]
                  const float* __restrict__ b0, const float* __restrict__ b1,
                  const float* __restrict__ b2,
                  const float* __restrict__ res,
                  const float* __restrict__ gamma, const float* __restrict__ beta,
                  float* __restrict__ out, __half* __restrict__ out16)
{
    int d = blockIdx.x * 8 + (threadIdx.x >> 5);
    int lane = threadIdx.x & 31;

    float total[4][4];
    #pragma unroll
    for (int j = 0; j < 4; j++)
        #pragma unroll
        for (int q = 0; q < 4; q++) total[j][q] = 0.f;

    for (int et = 0; et < 3; et++) {
        int o = off[et * NN + d];
        int n = deg[et * NN + d];
        const float* att = att_base + et * 512;
        const float4* pr = (const float4*)(xcat + (long)d * 3072 + 1536 + et * 512);

        float4 xr[4], t[4];
        #pragma unroll
        for (int j = 0; j < 4; j++) {
            xr[j] = pr[j * 32 + lane];
            t[j] = __ldg((const float4*)(att + (j * 2 + (lane >> 4)) * HID + (lane & 15) * 4));
        }
        float accv[4][4];
        float z[4] = {0.f, 0.f, 0.f, 0.f};
        #pragma unroll
        for (int j = 0; j < 4; j++)
            #pragma unroll
            for (int q = 0; q < 4; q++) accv[j][q] = 0.f;

        const int* srcs = csr + (long)et * EE + o;
        for (int k = 0; k < n; k++) {
            int s = srcs[k];
            const float4* pl = (const float4*)(xcat + (long)s * 3072 + et * 512);
            float4 a[4];
            #pragma unroll
            for (int j = 0; j < 4; j++) a[j] = pl[j * 32 + lane];
            #pragma unroll
            for (int j = 0; j < 4; j++) {
                float vx = a[j].x + xr[j].x; vx = vx > 0.f ? vx : 0.2f * vx;
                float vy = a[j].y + xr[j].y; vy = vy > 0.f ? vy : 0.2f * vy;
                float vz = a[j].z + xr[j].z; vz = vz > 0.f ? vz : 0.2f * vz;
                float vw = a[j].w + xr[j].w; vw = vw > 0.f ? vw : 0.2f * vw;
                float p = vx * t[j].x + vy * t[j].y + vz * t[j].z + vw * t[j].w;
                p += __shfl_xor_sync(0xffffffffu, p, 1);
                p += __shfl_xor_sync(0xffffffffu, p, 2);
                p += __shfl_xor_sync(0xffffffffu, p, 4);
                p += __shfl_xor_sync(0xffffffffu, p, 8);
                float w = expf(p);
                z[j] += w;
                accv[j][0] += w * a[j].x;
                accv[j][1] += w * a[j].y;
                accv[j][2] += w * a[j].z;
                accv[j][3] += w * a[j].w;
            }
        }
        #pragma unroll
        for (int j = 0; j < 4; j++) {
            float rz = z[j] != 0.f ? 1.f / z[j] : 0.f;
            total[j][0] += accv[j][0] * rz;
            total[j][1] += accv[j][1] * rz;
            total[j][2] += accv[j][2] * rz;
            total[j][3] += accv[j][3] * rz;
        }
    }

    // bias + ELU + residual; then warp-local LayerNorm over all 512 channels
    float s = 0.f, s2 = 0.f;
    #pragma unroll
    for (int j = 0; j < 4; j++) {
        int c = (j * 32 + lane) * 4;
        float4 bb0 = __ldg((const float4*)(b0 + c));
        float4 bb1 = __ldg((const float4*)(b1 + c));
        float4 bb2 = __ldg((const float4*)(b2 + c));
        float4 rr = *(const float4*)(res + (long)d * DH + c);
        float x0 = total[j][0] + bb0.x + bb1.x + bb2.x;
        float x1 = total[j][1] + bb0.y + bb1.y + bb2.y;
        float x2 = total[j][2] + bb0.z + bb1.z + bb2.z;
        float x3 = total[j][3] + bb0.w + bb1.w + bb2.w;
        x0 = (x0 > 0.f ? x0 : expm1f(x0)) + rr.x;
        x1 = (x1 > 0.f ? x1 : expm1f(x1)) + rr.y;
        x2 = (x2 > 0.f ? x2 : expm1f(x2)) + rr.z;
        x3 = (x3 > 0.f ? x3 : expm1f(x3)) + rr.w;
        total[j][0] = x0; total[j][1] = x1; total[j][2] = x2; total[j][3] = x3;
        s  += x0 + x1 + x2 + x3;
        s2 += x0 * x0 + x1 * x1 + x2 * x2 + x3 * x3;
    }
    s = warp_sum(s); s2 = warp_sum(s2);
    float mu = s * (1.f / DH);
    float var = s2 * (1.f / DH) - mu * mu;
    float inv = rsqrtf(var + 1e-5f);
    #pragma unroll
    for (int j = 0; j < 4; j++) {
        int c = (j * 32 + lane) * 4;
        float4 gg = __ldg((const float4*)(gamma + c));
        float4 bb = __ldg((const float4*)(beta + c));
        float o0 = (total[j][0] - mu) * inv * gg.x + bb.x;
        float o1 = (total[j][1] - mu) * inv * gg.y + bb.y;
        float o2 = (total[j][2] - mu) * inv * gg.z + bb.z;
        float o3 = (total[j][3] - mu) * inv * gg.w + bb.w;
        *(float4*)(out + (long)d * DH + c) = make_float4(o0, o1, o2, o3);
        union { __half2 h[2]; uint2 u; } p;
        p.h[0] = __floats2half2_rn(o0, o1);
        p.h[1] = __floats2half2_rn(o2, o3);
        *(uint2*)(out16 + (long)d * DH + c) = p.u;
    }
}

// ---------------- FULLY FUSED layer 2: agg(3 rel) + bias + ELU + LN ---------
__global__ __launch_bounds__(256)
void agg_fuse_l2(const float* __restrict__ xcat,
                 const int* __restrict__ off, const int* __restrict__ deg,
                 const int* __restrict__ csr,
                 const float* __restrict__ att_base,   // 3 x [256]
                 const float* __restrict__ b0, const float* __restrict__ b1,
                 const float* __restrict__ b2,
                 const float* __restrict__ gamma, const float* __restrict__ beta,
                 float* __restrict__ out)
{
    int d = blockIdx.x * 8 + (threadIdx.x >> 5);
    int lane = threadIdx.x & 31;

    float total[2][4];
    #pragma unroll
    for (int j = 0; j < 2; j++)
        #pragma unroll
        for (int q = 0; q < 4; q++) total[j][q] = 0.f;

    for (int et = 0; et < 3; et++) {
        int o = off[et * NN + d];
        int n = deg[et * NN + d];
        const float* att = att_base + et * 256;
        const float4* pr = (const float4*)(xcat + (long)d * 1536 + 768 + et * 256);

        float4 xr0 = pr[lane], xr1 = pr[32 + lane];
        float4 t0 = __ldg((const float4*)(att + lane * 4));
        float4 t1 = __ldg((const float4*)(att + 128 + lane * 4));

        float acc0[4] = {0.f, 0.f, 0.f, 0.f};
        float acc1[4] = {0.f, 0.f, 0.f, 0.f};
        float z = 0.f;

        const int* srcs = csr + (long)et * EE + o;
        for (int k = 0; k < n; k++) {
            int s = srcs[k];
            const float4* pl = (const float4*)(xcat + (long)s * 1536 + et * 256);
            float4 a0 = pl[lane], a1 = pl[32 + lane];
            float vx = a0.x + xr0.x; vx = vx > 0.f ? vx : 0.2f * vx;
            float vy = a0.y + xr0.y; vy = vy > 0.f ? vy : 0.2f * vy;
            float vz = a0.z + xr0.z; vz = vz > 0.f ? vz : 0.2f * vz;
            float vw = a0.w + xr0.w; vw = vw > 0.f ? vw : 0.2f * vw;
            float p = vx * t0.x + vy * t0.y + vz * t0.z + vw * t0.w;
            vx = a1.x + xr1.x; vx = vx > 0.f ? vx : 0.2f * vx;
            vy = a1.y + xr1.y; vy = vy > 0.f ? vy : 0.2f * vy;
            vz = a1.z + xr1.z; vz = vz > 0.f ? vz : 0.2f * vz;
            vw = a1.w + xr1.w; vw = vw > 0.f ? vw : 0.2f * vw;
            p += vx * t1.x + vy * t1.y + vz * t1.z + vw * t1.w;
            p = warp_sum(p);
            float w = expf(p);
            z += w;
            acc0[0] += w * a0.x; acc0[1] += w * a0.y;
            acc0[2] += w * a0.z; acc0[3] += w * a0.w;
            acc1[0] += w * a1.x; acc1[1] += w * a1.y;
            acc1[2] += w * a1.z; acc1[3] += w * a1.w;
        }
        float rz = z != 0.f ? 1.f / z : 0.f;
        #pragma unroll
        for (int q = 0; q < 4; q++) {
            total[0][q] += acc0[q] * rz;
            total[1][q] += acc1[q] * rz;
        }
    }

    float s = 0.f, s2 = 0.f;
    #pragma unroll
    for (int j = 0; j < 2; j++) {
        int c = (j * 32 + lane) * 4;
        float4 bb0 = __ldg((const float4*)(b0 + c));
        float4 bb1 = __ldg((const float4*)(b1 + c));
        float4 bb2 = __ldg((const float4*)(b2 + c));
        float x0 = total[j][0] + bb0.x + bb1.x + bb2.x;
        float x1 = total[j][1] + bb0.y + bb1.y + bb2.y;
        float x2 = total[j][2] + bb0.z + bb1.z + bb2.z;
        float x3 = total[j][3] + bb0.w + bb1.w + bb2.w;
        x0 = x0 > 0.f ? x0 : expm1f(x0);
        x1 = x1 > 0.f ? x1 : expm1f(x1);
        x2 = x2 > 0.f ? x2 : expm1f(x2);
        x3 = x3 > 0.f ? x3 : expm1f(x3);
        total[j][0] = x0; total[j][1] = x1; total[j][2] = x2; total[j][3] = x3;
        s  += x0 + x1 + x2 + x3;
        s2 += x0 * x0 + x1 * x1 + x2 * x2 + x3 * x3;
    }
    s = warp_sum(s); s2 = warp_sum(s2);
    float mu = s * (1.f / DOUT);
    float var = s2 * (1.f / DOUT) - mu * mu;
    float inv = rsqrtf(var + 1e-5f);
    #pragma unroll
    for (int j = 0; j < 2; j++) {
        int c = (j * 32 + lane) * 4;
        float4 gg = __ldg((const float4*)(gamma + c));
        float4 bb = __ldg((const float4*)(beta + c));
        float4 v;
        v.x = (total[j][0] - mu) * inv * gg.x + bb.x;
        v.y = (total[j][1] - mu) * inv * gg.y + bb.y;
        v.z = (total[j][2] - mu) * inv * gg.z + bb.z;
        v.w = (total[j][3] - mu) * inv * gg.w + bb.w;
        *(float4*)(out + (long)d * DOUT + c) = v;
    }
}

// ---------------- host ------------------------------------------------------
static inline void run_gemm(const __half* A, const __half* B, const float* bias,
                            float* C, __half* C16, int M, int N, int act)
{
    dim3 grid(N / GBN, (M + GBM - 1) / GBM);
    hgemm_bias_act<<<grid, 128, GEMM_SMEM>>>(A, B, bias, C, C16, M, N, act);
}

static inline void convert(const float* in, __half* out, long n)
{
    long n4 = n / 4;
    f32_to_f16<<<(unsigned)((n4 + 255) / 256), 256>>>(in, out, (int)n4);
}

extern "C" void kernel_launch(void* const* d_in, const int* in_sizes, int n_in,
                              void* d_out, int out_size)
{
    const float* x          = (const float*)d_in[0];
    const int*   edge_index = (const int*)  d_in[1];
    const float* proj_w     = (const float*)d_in[2];
    const float* proj_b     = (const float*)d_in[3];
    const float* l01_ll_w   = (const float*)d_in[4];
    const float* l01_ll_b   = (const float*)d_in[5];
    const float* l01_lr_w   = (const float*)d_in[6];
    const float* l01_lr_b   = (const float*)d_in[7];
    const float* l01_att    = (const float*)d_in[8];
    const float* l01_bias   = (const float*)d_in[9];
    const float* l2_ll_w    = (const float*)d_in[10];
    const float* l2_ll_b    = (const float*)d_in[11];
    const float* l2_lr_w    = (const float*)d_in[12];
    const float* l2_lr_b    = (const float*)d_in[13];
    const float* l2_att     = (const float*)d_in[14];
    const float* l2_bias    = (const float*)d_in[15];
    const float* ln01_gamma = (const float*)d_in[16];
    const float* ln01_beta  = (const float*)d_in[17];
    const float* ln2_gamma  = (const float*)d_in[18];
    const float* ln2_beta   = (const float*)d_in[19];

    float *h, *h2, *xcat, *bcat01, *bcat2;
    int *deg, *off, *cur, *csr;
    __half *a16, *x16, *w_proj, *wcat01, *wcat2;
    cudaGetSymbolAddress((void**)&h,      g_h);
    cudaGetSymbolAddress((void**)&h2,     g_h2);
    cudaGetSymbolAddress((void**)&xcat,   g_xcat);
    cudaGetSymbolAddress((void**)&deg,    g_deg);
    cudaGetSymbolAddress((void**)&off,    g_off);
    cudaGetSymbolAddress((void**)&cur,    g_cur);
    cudaGetSymbolAddress((void**)&csr,    g_csr);
    cudaGetSymbolAddress((void**)&a16,    g_a16);
    cudaGetSymbolAddress((void**)&x16,    g_x16);
    cudaGetSymbolAddress((void**)&w_proj, g_w16_proj);
    cudaGetSymbolAddress((void**)&wcat01, g_wcat01);
    cudaGetSymbolAddress((void**)&wcat2,  g_wcat2);
    cudaGetSymbolAddress((void**)&bcat01, g_bcat01);
    cudaGetSymbolAddress((void**)&bcat2,  g_bcat2);

    cudaFuncSetAttribute(hgemm_bias_act,
                         cudaFuncAttributeMaxDynamicSharedMemorySize, GEMM_SMEM);

    // one-time conversions / packs
    convert(x, x16, (long)NN * DH);
    convert(proj_w, w_proj, (long)DH * DH);
    pack_w01<<<(2 * 3 * DH * DH / 4 + 255) / 256, 256>>>(l01_ll_w, l01_lr_w, wcat01);
    pack_w2 <<<(3 * DH * DOUT / 4 + 255) / 256, 256>>>(l2_ll_w, l2_lr_w, wcat2);
    pack_b01<<<(2 * 3 * DH + 255) / 256, 256>>>(l01_ll_b, l01_lr_b, bcat01);
    pack_b2 <<<(3 * DOUT + 255) / 256, 256>>>(l2_ll_b, l2_lr_b, bcat2);

    // CSR build (reused by all 3 layers)
    cudaMemsetAsync(deg, 0, (size_t)3 * NN * sizeof(int));
    {
        dim3 grid((EE + 255) / 256, 3);
        deg_hist<<<grid, 256>>>(edge_index, deg);
        excl_scan<<<3, 512>>>(deg, off, cur);
        csr_fill<<<grid, 256>>>(edge_index, cur, csr);
    }

    // input projection + ELU (fp32 out h, fp16 out a16)
    run_gemm(x16, w_proj, proj_b, h, a16, NN, 512, 1);

    float* curh = h;
    float* nxt = h2;

    for (int li = 0; li < 2; li++) {
        run_gemm(a16, wcat01 + (size_t)li * DH * 3072, bcat01 + (size_t)li * 3072,
                 xcat, nullptr, NN, 3072, 0);
        agg_fuse_l01<<<NN / 8, 256>>>(xcat, off, deg, csr,
                                      l01_att + (size_t)li * 3 * HEADS * HID,
                                      l01_bias + (size_t)(li * 3 + 0) * DH,
                                      l01_bias + (size_t)(li * 3 + 1) * DH,
                                      l01_bias + (size_t)(li * 3 + 2) * DH,
                                      curh,
                                      ln01_gamma + (size_t)li * DH,
                                      ln01_beta  + (size_t)li * DH,
                                      nxt, a16);
        float* tmp = curh; curh = nxt; nxt = tmp;
    }

    // layer 2 (heads=1, out=256) -> d_out directly
    run_gemm(a16, wcat2, bcat2, xcat, nullptr, NN, 1536, 0);
    agg_fuse_l2<<<NN / 8, 256>>>(xcat, off, deg, csr, l2_att,
                                 l2_bias + 0 * DOUT, l2_bias + 1 * DOUT,
                                 l2_bias + 2 * DOUT,
                                 ln2_gamma, ln2_beta, (float*)d_out);
}